// round 4
// baseline (speedup 1.0000x reference)
#include <cuda_runtime.h>
#include <cuda_bf16.h>
#include <math.h>
#include <stdint.h>

// ---------------------------------------------------------------------------
// Problem dims (fixed by the dataset)
// ---------------------------------------------------------------------------
#define NP 2048   // pairs
#define NX 4096   // X/Y rows
#define DX 768    // X dim
#define DY 512    // Y dim
#define DF 256    // feature dim
#define EPS_INV 20.0f   // 1/0.05
#define SINK_IT 10

// acc slots
#define S_MARG 0
#define S_SAIL 1
#define S_EXP  2
#define S_IMP  3
#define S_OT   4
#define S_N1   5
#define S_N2   6
#define S_DT   7
#define S_SQA  8
#define S_SQB  9
#define S_SQG  10

// ---------------------------------------------------------------------------
// Static device scratch (no allocations allowed)
// ---------------------------------------------------------------------------
__device__ __align__(128) float g_Mp[(size_t)NP * NP];        // cos/eps for pairs
__device__ __align__(128) float g_Mu[(size_t)NX * NX];        // cos/eps latent
__device__ __align__(128) float g_Ca[(size_t)NX * NX];        // anchor-space M
__device__ __align__(128) float g_P [(size_t)NX * NX];        // plan_u
__device__ __align__(128) float g_Xa[NX * DX];
__device__ __align__(128) float g_Ya[NX * DY];
__device__ __align__(128) float g_Xu[NX * DX];
__device__ __align__(128) float g_Yu[NX * DY];
__device__ __align__(128) float g_Xn[NX * DX];
__device__ __align__(128) float g_Yn[NX * DY];
__device__ __align__(128) float g_fXn[NX * DF];
__device__ __align__(128) float g_fYn[NX * DF];
__device__ __align__(128) float g_fXpn[NP * DF];
__device__ __align__(128) float g_fYpn[NP * DF];
__device__ __align__(128) float g_W[NX * DX];                 // reused scratch
__device__ __align__(128) float g_T[NX * DY];                 // reused scratch
__device__ __align__(128) float g_Sxx[DX * DX];
__device__ __align__(128) float g_Syy[DY * DY];
__device__ __align__(128) float g_Sxy[DX * DY];
__device__ __align__(128) float g_Gxx[DX * DX];
__device__ __align__(128) float g_Gyy[DY * DY];
__device__ __align__(128) float g_Gfx[DF * DF];
__device__ __align__(128) float g_Gfy[DF * DF];
__device__ __align__(128) float g_Gxf[DX * DF];
__device__ __align__(128) float g_Gfyy[DF * DY];
__device__ __align__(128) float g_U1[DX * DY];
__device__ __align__(128) float g_V1[DX * DY];
__device__ __align__(128) float g_W1[DX * DY];
__device__ __align__(128) float g_Ag[DX * DX];
__device__ __align__(128) float g_Bg[DY * DY];
__device__ __align__(128) float g_Gg[DX * DY];
__device__ float g_up[NP], g_vp[NP];
__device__ float g_uu[NX], g_vu[NX];
__device__ float g_ua[NX], g_va[NX];
__device__ float g_arow[NX], g_bcol[NX];
__device__ float g_ap[NP], g_bp[NP];
__device__ __align__(128) float g_pm[16 * NX], g_ps[16 * NX];
__device__ double g_acc[16];

// ---------------------------------------------------------------------------
// Reduction helpers
// ---------------------------------------------------------------------------
__device__ __forceinline__ float warpSum(float v) {
    #pragma unroll
    for (int o = 16; o; o >>= 1) v += __shfl_xor_sync(0xffffffffu, v, o);
    return v;
}
__device__ __forceinline__ double warpSumD(double v) {
    #pragma unroll
    for (int o = 16; o; o >>= 1) v += __shfl_xor_sync(0xffffffffu, v, o);
    return v;
}
__device__ float blockSum(float v) {
    __shared__ float s[32];
    __syncthreads();
    int lane = threadIdx.x & 31, wid = threadIdx.x >> 5;
    v = warpSum(v);
    if (lane == 0) s[wid] = v;
    __syncthreads();
    if (wid == 0) {
        int nw = blockDim.x >> 5;
        v = (lane < nw) ? s[lane] : 0.f;
        v = warpSum(v);
    }
    return v;
}
__device__ double blockSumD(double v) {
    __shared__ double s[32];
    __syncthreads();
    int lane = threadIdx.x & 31, wid = threadIdx.x >> 5;
    v = warpSumD(v);
    if (lane == 0) s[wid] = v;
    __syncthreads();
    if (wid == 0) {
        int nw = blockDim.x >> 5;
        v = (lane < nw) ? s[lane] : 0.0;
        v = warpSumD(v);
    }
    return v;
}

__device__ __forceinline__ void lse_combine(float& m, float& s, float m2, float s2) {
    if (m2 == -INFINITY) return;
    if (m == -INFINITY) { m = m2; s = s2; return; }
    float mn = fmaxf(m, m2);
    s = s * expf(m - mn) + s2 * expf(m2 - mn);
    m = mn;
}
__device__ void blockLSE(float& m, float& s) {
    __shared__ float sm[32], ss[32];
    __syncthreads();
    int lane = threadIdx.x & 31, wid = threadIdx.x >> 5;
    #pragma unroll
    for (int o = 16; o; o >>= 1) {
        float m2 = __shfl_xor_sync(0xffffffffu, m, o);
        float s2 = __shfl_xor_sync(0xffffffffu, s, o);
        lse_combine(m, s, m2, s2);
    }
    if (lane == 0) { sm[wid] = m; ss[wid] = s; }
    __syncthreads();
    if (wid == 0) {
        int nw = blockDim.x >> 5;
        m = (lane < nw) ? sm[lane] : -INFINITY;
        s = (lane < nw) ? ss[lane] : 0.f;
        #pragma unroll
        for (int o = 16; o; o >>= 1) {
            float m2 = __shfl_xor_sync(0xffffffffu, m, o);
            float s2 = __shfl_xor_sync(0xffffffffu, s, o);
            lse_combine(m, s, m2, s2);
        }
    }
}

// ---------------------------------------------------------------------------
// Tensor-core GEMM with split-bf16 (bf16x3) emulated fp32.
// C[M,N] = alpha * sum_k opA(m,k)*opB(k,n)
// TA=0: A row-major MxK ; TA=1: A row-major KxM (A^T)
// TB=0: B row-major KxN ; TB=1: B row-major NxK (B^T)
// Requires: M,N % 128 == 0, K % 16 == 0, lds % 4 == 0.
// 256 threads (8 warps), block tile 128x128, warp tile 64x32, K-step 16.
// ---------------------------------------------------------------------------
#define ASTRIDE 24   // bf16 elements per smem row (16 used + 8 pad) -> conflict-free

__device__ __forceinline__ void bsplit(float x, __nv_bfloat16& h, __nv_bfloat16& l) {
    h = __float2bfloat16(x);
    l = __float2bfloat16(x - __bfloat162float(h));
}
__device__ __forceinline__ uint32_t bpack(__nv_bfloat16 a, __nv_bfloat16 b) {
    __nv_bfloat162 t; t.x = a; t.y = b;
    return *reinterpret_cast<uint32_t*>(&t);
}
__device__ __forceinline__ void mma16816(float* c, const uint32_t* a, const uint32_t* b) {
    asm volatile(
        "mma.sync.aligned.m16n8k16.row.col.f32.bf16.bf16.f32 "
        "{%0,%1,%2,%3}, {%4,%5,%6,%7}, {%8,%9}, {%0,%1,%2,%3};\n"
        : "+f"(c[0]), "+f"(c[1]), "+f"(c[2]), "+f"(c[3])
        : "r"(a[0]), "r"(a[1]), "r"(a[2]), "r"(a[3]), "r"(b[0]), "r"(b[1]));
}

template <int TA, int TB>
__global__ __launch_bounds__(256, 2)
void gemm_mma_kernel(const float* __restrict__ A, const float* __restrict__ B,
                     float* __restrict__ C, int K,
                     int lda, int ldb, int ldc, float alpha) {
    __shared__ __align__(16) __nv_bfloat16 Ash[128][ASTRIDE];
    __shared__ __align__(16) __nv_bfloat16 Asl[128][ASTRIDE];
    __shared__ __align__(16) __nv_bfloat16 Bsh[128][ASTRIDE];
    __shared__ __align__(16) __nv_bfloat16 Bsl[128][ASTRIDE];

    const int tid = threadIdx.x;
    const int warp = tid >> 5, lane = tid & 31;
    const int bm = blockIdx.y * 128, bn = blockIdx.x * 128;
    const int wm = (warp >> 2) * 64;   // 0 or 64
    const int wn = (warp & 3) * 32;    // 0,32,64,96

    float acc[4][4][4];
    #pragma unroll
    for (int mi = 0; mi < 4; mi++)
        #pragma unroll
        for (int ni = 0; ni < 4; ni++)
            #pragma unroll
            for (int e = 0; e < 4; e++) acc[mi][ni][e] = 0.f;

    for (int k0 = 0; k0 < K; k0 += 16) {
        // ---- stage A tile (rows m 0..127, cols k 0..15) as hi/lo bf16 ----
        if (TA == 0) {
            #pragma unroll
            for (int i = 0; i < 2; i++) {
                int f = tid * 2 + i;              // 0..511
                int row = f >> 2, c4 = (f & 3) * 4;
                float4 v = *(const float4*)&A[(size_t)(bm + row) * lda + k0 + c4];
                __nv_bfloat16 h0, h1, h2, h3, l0, l1, l2, l3;
                bsplit(v.x, h0, l0); bsplit(v.y, h1, l1);
                bsplit(v.z, h2, l2); bsplit(v.w, h3, l3);
                *(uint2*)&Ash[row][c4] = make_uint2(bpack(h0, h1), bpack(h2, h3));
                *(uint2*)&Asl[row][c4] = make_uint2(bpack(l0, l1), bpack(l2, l3));
            }
        } else {
            #pragma unroll
            for (int i = 0; i < 2; i++) {
                int f = tid * 2 + i;
                int kr = f >> 5, m0 = (f & 31) * 4;
                float4 v = *(const float4*)&A[(size_t)(k0 + kr) * lda + bm + m0];
                __nv_bfloat16 h, l;
                bsplit(v.x, h, l); Ash[m0 + 0][kr] = h; Asl[m0 + 0][kr] = l;
                bsplit(v.y, h, l); Ash[m0 + 1][kr] = h; Asl[m0 + 1][kr] = l;
                bsplit(v.z, h, l); Ash[m0 + 2][kr] = h; Asl[m0 + 2][kr] = l;
                bsplit(v.w, h, l); Ash[m0 + 3][kr] = h; Asl[m0 + 3][kr] = l;
            }
        }
        // ---- stage B tile as Bs[n][k] (k-contiguous) hi/lo ----
        if (TB == 1) {
            #pragma unroll
            for (int i = 0; i < 2; i++) {
                int f = tid * 2 + i;
                int row = f >> 2, c4 = (f & 3) * 4;
                float4 v = *(const float4*)&B[(size_t)(bn + row) * ldb + k0 + c4];
                __nv_bfloat16 h0, h1, h2, h3, l0, l1, l2, l3;
                bsplit(v.x, h0, l0); bsplit(v.y, h1, l1);
                bsplit(v.z, h2, l2); bsplit(v.w, h3, l3);
                *(uint2*)&Bsh[row][c4] = make_uint2(bpack(h0, h1), bpack(h2, h3));
                *(uint2*)&Bsl[row][c4] = make_uint2(bpack(l0, l1), bpack(l2, l3));
            }
        } else {
            #pragma unroll
            for (int i = 0; i < 2; i++) {
                int f = tid * 2 + i;
                int kr = f >> 5, n0 = (f & 31) * 4;
                float4 v = *(const float4*)&B[(size_t)(k0 + kr) * ldb + bn + n0];
                __nv_bfloat16 h, l;
                bsplit(v.x, h, l); Bsh[n0 + 0][kr] = h; Bsl[n0 + 0][kr] = l;
                bsplit(v.y, h, l); Bsh[n0 + 1][kr] = h; Bsl[n0 + 1][kr] = l;
                bsplit(v.z, h, l); Bsh[n0 + 2][kr] = h; Bsl[n0 + 2][kr] = l;
                bsplit(v.w, h, l); Bsh[n0 + 3][kr] = h; Bsl[n0 + 3][kr] = l;
            }
        }
        __syncthreads();

        // ---- compute: 48 MMAs per warp per k16 ----
        const int fr = lane >> 2;          // 0..7
        const int fc = (lane & 3) * 2;     // 0,2,4,6
        uint32_t bh[4][2], bl[4][2];
        #pragma unroll
        for (int ni = 0; ni < 4; ni++) {
            int nr = wn + ni * 8 + fr;
            bh[ni][0] = *(const uint32_t*)&Bsh[nr][fc];
            bh[ni][1] = *(const uint32_t*)&Bsh[nr][fc + 8];
            bl[ni][0] = *(const uint32_t*)&Bsl[nr][fc];
            bl[ni][1] = *(const uint32_t*)&Bsl[nr][fc + 8];
        }
        #pragma unroll
        for (int mi = 0; mi < 4; mi++) {
            int r0 = wm + mi * 16 + fr;
            uint32_t ah[4], al[4];
            ah[0] = *(const uint32_t*)&Ash[r0][fc];
            ah[1] = *(const uint32_t*)&Ash[r0 + 8][fc];
            ah[2] = *(const uint32_t*)&Ash[r0][fc + 8];
            ah[3] = *(const uint32_t*)&Ash[r0 + 8][fc + 8];
            al[0] = *(const uint32_t*)&Asl[r0][fc];
            al[1] = *(const uint32_t*)&Asl[r0 + 8][fc];
            al[2] = *(const uint32_t*)&Asl[r0][fc + 8];
            al[3] = *(const uint32_t*)&Asl[r0 + 8][fc + 8];
            #pragma unroll
            for (int ni = 0; ni < 4; ni++) {
                mma16816(acc[mi][ni], ah, bh[ni]);   // hi*hi
                mma16816(acc[mi][ni], ah, bl[ni]);   // hi*lo
                mma16816(acc[mi][ni], al, bh[ni]);   // lo*hi
            }
        }
        __syncthreads();
    }

    // ---- epilogue ----
    const int fr = lane >> 2;
    const int fc = (lane & 3) * 2;
    #pragma unroll
    for (int mi = 0; mi < 4; mi++) {
        int r = bm + wm + mi * 16 + fr;
        #pragma unroll
        for (int ni = 0; ni < 4; ni++) {
            int c = bn + wn + ni * 8 + fc;
            float2 v0, v1;
            v0.x = alpha * acc[mi][ni][0];
            v0.y = alpha * acc[mi][ni][1];
            v1.x = alpha * acc[mi][ni][2];
            v1.y = alpha * acc[mi][ni][3];
            *(float2*)&C[(size_t)r * ldc + c] = v0;
            *(float2*)&C[(size_t)(r + 8) * ldc + c] = v1;
        }
    }
}

// ---------------------------------------------------------------------------
// Elementwise / reduction kernels
// ---------------------------------------------------------------------------
__global__ void zero_acc_kernel(double* a) { if (threadIdx.x < 16) a[threadIdx.x] = 0.0; }
__global__ void zero_vec_kernel(float* p, int n) {
    int i = blockIdx.x * blockDim.x + threadIdx.x;
    if (i < n) p[i] = 0.f;
}

__global__ void rownorm_kernel(const float* __restrict__ in, float* __restrict__ out, int D) {
    int row = blockIdx.x;
    const float* r = in + (size_t)row * D;
    float ss = 0.f;
    for (int i = threadIdx.x; i < D; i += blockDim.x) { float v = r[i]; ss += v * v; }
    ss = blockSum(ss);
    __shared__ float s_inv;
    if (threadIdx.x == 0) s_inv = 1.f / fmaxf(sqrtf(ss), 1e-8f);
    __syncthreads();
    float inv = s_inv;
    for (int i = threadIdx.x; i < D; i += blockDim.x) out[(size_t)row * D + i] = r[i] * inv;
}

__global__ void quadnorm_kernel(const float* __restrict__ X, const float* __restrict__ W,
                                float* __restrict__ out, int D) {
    int row = blockIdx.x;
    const float* xr = X + (size_t)row * D;
    const float* wr = W + (size_t)row * D;
    float ss = 0.f;
    for (int i = threadIdx.x; i < D; i += blockDim.x) ss += xr[i] * wr[i];
    ss = blockSum(ss);
    __shared__ float s_inv;
    if (threadIdx.x == 0) s_inv = 1.f / fmaxf(sqrtf(ss), 1e-8f);
    __syncthreads();
    float inv = s_inv;
    for (int i = threadIdx.x; i < D; i += blockDim.x) out[(size_t)row * D + i] = xr[i] * inv;
}

__global__ void scale_rows_sqrt_kernel(const float* __restrict__ X, const float* __restrict__ a,
                                       float* __restrict__ out, int D) {
    int row = blockIdx.x;
    float sc = sqrtf(fmaxf(a[row], 0.f));
    for (int i = threadIdx.x; i < D; i += blockDim.x)
        out[(size_t)row * D + i] = X[(size_t)row * D + i] * sc;
}

__global__ void row_lse_kernel(const float* __restrict__ M, const float* __restrict__ v,
                               float* __restrict__ u, int ny, float log_a) {
    int row = blockIdx.x;
    const float* Mr = M + (size_t)row * ny;
    float m = -INFINITY, s = 0.f;
    for (int c = threadIdx.x; c < ny; c += blockDim.x) {
        float x = Mr[c] + v[c];
        float mn = fmaxf(m, x);
        s = s * expf(m - mn) + expf(x - mn);
        m = mn;
    }
    blockLSE(m, s);
    if (threadIdx.x == 0) u[row] = log_a - (m + logf(s));
}

__global__ void col_lse_partial_kernel(const float* __restrict__ M, const float* __restrict__ u,
                                       float* __restrict__ pm, float* __restrict__ ps,
                                       int nx, int ny, int chunk) {
    int col = blockIdx.x * blockDim.x + threadIdx.x;
    int r0 = blockIdx.y * chunk;
    int r1 = min(r0 + chunk, nx);
    float m = -INFINITY, s = 0.f;
    for (int r = r0; r < r1; r++) {
        float x = M[(size_t)r * ny + col] + __ldg(&u[r]);
        float mn = fmaxf(m, x);
        s = s * expf(m - mn) + expf(x - mn);
        m = mn;
    }
    pm[(size_t)blockIdx.y * ny + col] = m;
    ps[(size_t)blockIdx.y * ny + col] = s;
}

__global__ void col_lse_combine_kernel(const float* __restrict__ pm, const float* __restrict__ ps,
                                       float* __restrict__ v, int ny, int nch, float log_b) {
    int col = blockIdx.x * blockDim.x + threadIdx.x;
    float m = -INFINITY, s = 0.f;
    for (int c = 0; c < nch; c++)
        lse_combine(m, s, pm[(size_t)c * ny + col], ps[(size_t)c * ny + col]);
    v[col] = log_b - (m + logf(s));
}

__global__ void plan_rowsum_kernel(const float* __restrict__ M, const float* __restrict__ u,
                                   const float* __restrict__ v, float* __restrict__ rowsum,
                                   float* __restrict__ P, int ny) {
    int row = blockIdx.x;
    float uv = u[row];
    const float* Mr = M + (size_t)row * ny;
    float s = 0.f;
    for (int c = threadIdx.x; c < ny; c += blockDim.x) {
        float p = expf(Mr[c] + uv + v[c]);
        if (P) P[(size_t)row * ny + c] = p;
        s += p;
    }
    s = blockSum(s);
    if (threadIdx.x == 0) rowsum[row] = s;
}

__global__ void plan_colsum_partial_kernel(const float* __restrict__ M, const float* __restrict__ u,
                                           const float* __restrict__ v, float* __restrict__ ps,
                                           int nx, int ny, int chunk) {
    int col = blockIdx.x * blockDim.x + threadIdx.x;
    int r0 = blockIdx.y * chunk;
    int r1 = min(r0 + chunk, nx);
    float vc = v[col];
    float s = 0.f;
    for (int r = r0; r < r1; r++)
        s += expf(M[(size_t)r * ny + col] + __ldg(&u[r]) + vc);
    ps[(size_t)blockIdx.y * ny + col] = s;
}

__global__ void colsum_combine_kernel(const float* __restrict__ ps, float* __restrict__ b,
                                      int ny, int nch) {
    int col = blockIdx.x * blockDim.x + threadIdx.x;
    float s = 0.f;
    for (int c = 0; c < nch; c++) s += ps[(size_t)c * ny + col];
    b[col] = s;
}

__global__ void marg_acc_kernel(const float* __restrict__ sums, int n, double* acc) {
    int i = blockIdx.x * blockDim.x + threadIdx.x;
    double t = 0.0;
    if (i < n) {
        float d = sums[i] - 1.f / (float)n;
        t = (double)d * (double)d;
    }
    t = blockSumD(t);
    if (threadIdx.x == 0) atomicAdd(&acc[S_MARG], t);
}

__global__ void sail_acc_kernel(const float* __restrict__ Mp, int n, double* acc) {
    size_t total = (size_t)n * n;
    double t = 0.0;
    for (size_t idx = (size_t)blockIdx.x * blockDim.x + threadIdx.x; idx < total;
         idx += (size_t)gridDim.x * blockDim.x) {
        int i = (int)(idx / n), j = (int)(idx - (size_t)i * n);
        float z = Mp[idx] * 0.5f;
        if (i != j) z = -z;
        float a = -z;
        float sp = fmaxf(a, 0.f) + log1pf(expf(-fabsf(a)));
        t += (double)sp;
    }
    t = blockSumD(t);
    if (threadIdx.x == 0) atomicAdd(&acc[S_SAIL], t);
}

__global__ void diag_acc_kernel(const float* __restrict__ Mp, const float* __restrict__ u,
                                const float* __restrict__ v, int n, float logN, double* acc) {
    int i = blockIdx.x * blockDim.x + threadIdx.x;
    double ti = 0.0, te = 0.0;
    if (i < n) {
        float mii = Mp[(size_t)i * n + i];
        ti = (double)(mii + u[i] + v[i] + logN);
        te = (double)((1.f - mii * 0.05f) * 0.5f);
    }
    ti = blockSumD(ti);
    __shared__ double sh;
    if (threadIdx.x == 0) sh = ti;
    te = blockSumD(te);
    if (threadIdx.x == 0) {
        atomicAdd(&acc[S_IMP], sh);
        atomicAdd(&acc[S_EXP], te);
    }
}

__global__ void ot_acc_kernel(const float* __restrict__ Ca, const float* __restrict__ Mu,
                              const float* __restrict__ ua, const float* __restrict__ va,
                              const float* __restrict__ uu, const float* __restrict__ vu,
                              int n, double* acc) {
    size_t total = (size_t)n * n;
    double t = 0.0;
    for (size_t idx = (size_t)blockIdx.x * blockDim.x + threadIdx.x; idx < total;
         idx += (size_t)gridDim.x * blockDim.x) {
        int i = (int)(idx / n), j = (int)(idx - (size_t)i * n);
        float la = Ca[idx] + ua[i] + va[j];
        float lu = Mu[idx] + uu[i] + vu[j];
        t += (double)(expf(la) * (la - lu));
    }
    t = blockSumD(t);
    if (threadIdx.x == 0) atomicAdd(&acc[S_OT], t);
}

__global__ void dot_acc_kernel(const float* __restrict__ A, const float* __restrict__ B,
                               int n, double* acc, int slot) {
    double t = 0.0;
    for (int i = blockIdx.x * blockDim.x + threadIdx.x; i < n; i += gridDim.x * blockDim.x)
        t += (double)A[i] * (double)B[i];
    t = blockSumD(t);
    if (threadIdx.x == 0) atomicAdd(&acc[slot], t);
}

__global__ void sumsq_acc_kernel(const float* __restrict__ A, int n, double* acc, int slot) {
    double t = 0.0;
    for (int i = blockIdx.x * blockDim.x + threadIdx.x; i < n; i += gridDim.x * blockDim.x)
        t += (double)A[i] * (double)A[i];
    t = blockSumD(t);
    if (threadIdx.x == 0) atomicAdd(&acc[slot], t);
}

__global__ void finalize_kernel(const double* __restrict__ acc, float* __restrict__ out) {
    double L = acc[S_MARG]
             + acc[S_SAIL] / ((double)NP * (double)NP)
             + acc[S_EXP] / (double)NP
             - acc[S_IMP] / (double)NP
             + acc[S_OT]
             + (acc[S_N1] + acc[S_N2] - 2.0 * acc[S_DT]) / ((double)NX * (double)NX)
             + (acc[S_SQA] + acc[S_SQB] - 2.0 * acc[S_SQG]);
    out[0] = (float)L;
}

// ---------------------------------------------------------------------------
// Host side
// ---------------------------------------------------------------------------
static inline void launch_gemm(int TA, int TB, const float* A, const float* B, float* C,
                               int M, int N, int K, int lda, int ldb, int ldc, float alpha) {
    dim3 grid(N / 128, M / 128), block(256);
    if (TA == 0 && TB == 0) gemm_mma_kernel<0, 0><<<grid, block>>>(A, B, C, K, lda, ldb, ldc, alpha);
    else if (TA == 0 && TB == 1) gemm_mma_kernel<0, 1><<<grid, block>>>(A, B, C, K, lda, ldb, ldc, alpha);
    else gemm_mma_kernel<1, 0><<<grid, block>>>(A, B, C, K, lda, ldb, ldc, alpha);
}

static void run_sinkhorn(float* M, float* u, float* v, int nx, int ny, float* pm, float* ps) {
    float log_a = -logf((float)nx), log_b = -logf((float)ny);
    const int CH = 256;
    int nch = nx / CH;
    zero_vec_kernel<<<(ny + 255) / 256, 256>>>(v, ny);
    dim3 cgrid(ny / 256, nch);
    for (int it = 0; it < SINK_IT; it++) {
        row_lse_kernel<<<nx, 256>>>(M, v, u, ny, log_a);
        col_lse_partial_kernel<<<cgrid, 256>>>(M, u, pm, ps, nx, ny, CH);
        col_lse_combine_kernel<<<ny / 256, 256>>>(pm, ps, v, ny, nch, log_b);
    }
}

#define GETSYM(ptr, sym) do { void* _t; cudaGetSymbolAddress(&_t, sym); ptr = (float*)_t; } while (0)

extern "C" void kernel_launch(void* const* d_in, const int* in_sizes, int n_in,
                              void* d_out, int out_size) {
    const float* fXp = (const float*)d_in[0];   // 2048x256
    const float* fYp = (const float*)d_in[1];   // 2048x256
    const float* X   = (const float*)d_in[2];   // 4096x768
    const float* Y   = (const float*)d_in[3];   // 4096x512
    const float* fX  = (const float*)d_in[4];   // 4096x256
    const float* fY  = (const float*)d_in[5];   // 4096x256
    const float* Xan = (const float*)d_in[6];   // 4096x768
    const float* Yan = (const float*)d_in[7];   // 4096x512
    float* out = (float*)d_out;

    float *Mp, *Mu, *Ca, *P, *Xa, *Ya, *Xu, *Yu, *Xn, *Yn, *fXn, *fYn, *fXpn, *fYpn;
    float *W, *T, *Sxx, *Syy, *Sxy, *Gxx, *Gyy, *Gfx, *Gfy, *Gxf, *Gfyy, *U1, *V1, *W1;
    float *Ag, *Bg, *Gg, *up, *vp, *uu, *vu, *ua, *va, *arow, *bcol, *ap, *bp, *pm, *ps;
    double* acc;
    GETSYM(Mp, g_Mp); GETSYM(Mu, g_Mu); GETSYM(Ca, g_Ca); GETSYM(P, g_P);
    GETSYM(Xa, g_Xa); GETSYM(Ya, g_Ya); GETSYM(Xu, g_Xu); GETSYM(Yu, g_Yu);
    GETSYM(Xn, g_Xn); GETSYM(Yn, g_Yn); GETSYM(fXn, g_fXn); GETSYM(fYn, g_fYn);
    GETSYM(fXpn, g_fXpn); GETSYM(fYpn, g_fYpn);
    GETSYM(W, g_W); GETSYM(T, g_T);
    GETSYM(Sxx, g_Sxx); GETSYM(Syy, g_Syy); GETSYM(Sxy, g_Sxy);
    GETSYM(Gxx, g_Gxx); GETSYM(Gyy, g_Gyy); GETSYM(Gfx, g_Gfx); GETSYM(Gfy, g_Gfy);
    GETSYM(Gxf, g_Gxf); GETSYM(Gfyy, g_Gfyy); GETSYM(U1, g_U1); GETSYM(V1, g_V1); GETSYM(W1, g_W1);
    GETSYM(Ag, g_Ag); GETSYM(Bg, g_Bg); GETSYM(Gg, g_Gg);
    GETSYM(up, g_up); GETSYM(vp, g_vp); GETSYM(uu, g_uu); GETSYM(vu, g_vu);
    GETSYM(ua, g_ua); GETSYM(va, g_va);
    GETSYM(arow, g_arow); GETSYM(bcol, g_bcol); GETSYM(ap, g_ap); GETSYM(bp, g_bp);
    GETSYM(pm, g_pm); GETSYM(ps, g_ps);
    { void* _t; cudaGetSymbolAddress(&_t, g_acc); acc = (double*)_t; }

    zero_acc_kernel<<<1, 32>>>(acc);

    // --- row norms ---
    rownorm_kernel<<<NX, 256>>>(Xan, Xa, DX);
    rownorm_kernel<<<NX, 256>>>(Yan, Ya, DY);
    rownorm_kernel<<<NP, 256>>>(fXp, fXpn, DF);
    rownorm_kernel<<<NP, 256>>>(fYp, fYpn, DF);
    rownorm_kernel<<<NX, 256>>>(fX, fXn, DF);
    rownorm_kernel<<<NX, 256>>>(fY, fYn, DF);
    rownorm_kernel<<<NX, 256>>>(X, Xu, DX);
    rownorm_kernel<<<NX, 256>>>(Y, Yu, DY);

    // --- anchor covariances ---
    launch_gemm(1, 0, Xa, Xa, Sxx, DX, DX, NX, DX, DX, DX, 1.f / NX);
    launch_gemm(1, 0, Ya, Ya, Syy, DY, DY, NX, DY, DY, DY, 1.f / NX);
    launch_gemm(1, 0, Xa, Ya, Sxy, DX, DY, NX, DX, DY, DY, 1.f / NX);

    // --- cosine/eps matrices ---
    launch_gemm(0, 1, fXpn, fYpn, Mp, NP, NP, DF, DF, DF, NP, EPS_INV);
    launch_gemm(0, 1, fXn, fYn, Mu, NX, NX, DF, DF, DF, NX, EPS_INV);

    // --- shared-space sinkhorns ---
    run_sinkhorn(Mp, up, vp, NP, NP, pm, ps);
    run_sinkhorn(Mu, uu, vu, NX, NX, pm, ps);

    // --- pairs plan stats: marginals + SAIL + diag losses ---
    plan_rowsum_kernel<<<NP, 256>>>(Mp, up, vp, ap, nullptr, NP);
    plan_colsum_partial_kernel<<<dim3(NP / 256, NP / 256), 256>>>(Mp, up, vp, ps, NP, NP, 256);
    colsum_combine_kernel<<<NP / 256, 256>>>(ps, bp, NP, NP / 256);
    marg_acc_kernel<<<NP / 256, 256>>>(ap, NP, acc);
    marg_acc_kernel<<<NP / 256, 256>>>(bp, NP, acc);
    sail_acc_kernel<<<1024, 256>>>(Mp, NP, acc);
    diag_acc_kernel<<<NP / 256, 256>>>(Mp, up, vp, NP, logf((float)NP), acc);

    // --- latent plan stats (and materialize plan_u) ---
    plan_rowsum_kernel<<<NX, 256>>>(Mu, uu, vu, arow, P, NX);
    plan_colsum_partial_kernel<<<dim3(NX / 256, NX / 256), 256>>>(Mu, uu, vu, ps, NX, NX, 256);
    colsum_combine_kernel<<<NX / 256, 256>>>(ps, bcol, NX, NX / 256);
    marg_acc_kernel<<<NX / 256, 256>>>(arow, NX, acc);
    marg_acc_kernel<<<NX / 256, 256>>>(bcol, NX, acc);

    // --- anchor-space normalization + plan ---
    launch_gemm(0, 0, X, Sxx, W, NX, DX, DX, DX, DX, DX, 1.f);
    quadnorm_kernel<<<NX, 256>>>(X, W, Xn, DX);
    launch_gemm(0, 0, Y, Syy, W, NX, DY, DY, DY, DY, DY, 1.f);
    quadnorm_kernel<<<NX, 256>>>(Y, W, Yn, DY);
    launch_gemm(0, 0, Xn, Sxy, T, NX, DY, DX, DX, DY, DY, 1.f);
    launch_gemm(0, 1, T, Yn, Ca, NX, NX, DY, DY, DY, NX, EPS_INV);
    run_sinkhorn(Ca, ua, va, NX, NX, pm, ps);

    // --- L_ot ---
    ot_acc_kernel<<<2048, 256>>>(Ca, Mu, ua, va, uu, vu, NX, acc);

    // --- L_div ---
    launch_gemm(1, 0, Xn, Xn, Gxx, DX, DX, NX, DX, DX, DX, 1.f);
    launch_gemm(1, 0, Yn, Yn, Gyy, DY, DY, NX, DY, DY, DY, 1.f);
    launch_gemm(1, 0, fXn, fXn, Gfx, DF, DF, NX, DF, DF, DF, 1.f);
    launch_gemm(1, 0, fYn, fYn, Gfy, DF, DF, NX, DF, DF, DF, 1.f);
    launch_gemm(1, 0, Xn, fXn, Gxf, DX, DF, NX, DX, DF, DF, 1.f);
    launch_gemm(1, 0, fYn, Yn, Gfyy, DF, DY, NX, DF, DY, DY, 1.f);
    launch_gemm(0, 0, Gxx, Sxy, U1, DX, DY, DX, DX, DY, DY, 1.f);
    launch_gemm(0, 0, U1, Gyy, V1, DX, DY, DY, DY, DY, DY, 1.f);
    launch_gemm(0, 0, Gxf, Gfyy, W1, DX, DY, DF, DF, DY, DY, 1.f);
    dot_acc_kernel<<<256, 256>>>(V1, Sxy, DX * DY, acc, S_N1);
    dot_acc_kernel<<<256, 256>>>(Gfx, Gfy, DF * DF, acc, S_N2);
    dot_acc_kernel<<<256, 256>>>(W1, Sxy, DX * DY, acc, S_DT);

    // --- L_gw ---
    scale_rows_sqrt_kernel<<<NX, 256>>>(Xu, arow, W, DX);
    launch_gemm(1, 0, W, W, Ag, DX, DX, NX, DX, DX, DX, 1.f);
    sumsq_acc_kernel<<<256, 256>>>(Ag, DX * DX, acc, S_SQA);
    scale_rows_sqrt_kernel<<<NX, 256>>>(Yu, bcol, W, DY);
    launch_gemm(1, 0, W, W, Bg, DY, DY, NX, DY, DY, DY, 1.f);
    sumsq_acc_kernel<<<256, 256>>>(Bg, DY * DY, acc, S_SQB);
    launch_gemm(0, 0, P, Yu, T, NX, DY, NX, NX, DY, DY, 1.f);   // PY = plan_u @ Yu
    launch_gemm(1, 0, Xu, T, Gg, DX, DY, NX, DX, DY, DY, 1.f);  // G = Xu^T @ PY
    sumsq_acc_kernel<<<256, 256>>>(Gg, DX * DY, acc, S_SQG);

    finalize_kernel<<<1, 1>>>(acc, out);
}

// round 7
// speedup vs baseline: 1.1626x; 1.1626x over previous
#include <cuda_runtime.h>
#include <cuda_bf16.h>
#include <math.h>
#include <stdint.h>

// ---------------------------------------------------------------------------
// Problem dims (fixed by the dataset)
// ---------------------------------------------------------------------------
#define NP 2048   // pairs
#define NX 4096   // X/Y rows
#define DX 768    // X dim
#define DY 512    // Y dim
#define DF 256    // feature dim
#define EPS_INV 20.0f   // 1/0.05
#define SINK_IT 10
#define LSE_C 20.0f     // constant shift: |M| <= 20 provably

// acc slots
#define S_MARG 0
#define S_SAIL 1
#define S_EXP  2
#define S_IMP  3
#define S_OT   4
#define S_N1   5
#define S_N2   6
#define S_DT   7
#define S_SQA  8
#define S_SQB  9
#define S_SQG  10

// ---------------------------------------------------------------------------
// Static device scratch (no allocations allowed)
// ---------------------------------------------------------------------------
__device__ __align__(128) float g_Mp[(size_t)NP * NP];
__device__ __align__(128) float g_Mu[(size_t)NX * NX];
__device__ __align__(128) float g_Ca[(size_t)NX * NX];
__device__ __align__(128) float g_P [(size_t)NX * NX];
__device__ __align__(128) float g_Xa[NX * DX];
__device__ __align__(128) float g_Ya[NX * DY];
__device__ __align__(128) float g_Xu[NX * DX];
__device__ __align__(128) float g_Yu[NX * DY];
__device__ __align__(128) float g_Xn[NX * DX];
__device__ __align__(128) float g_Yn[NX * DY];
__device__ __align__(128) float g_fXn[NX * DF];
__device__ __align__(128) float g_fYn[NX * DF];
__device__ __align__(128) float g_fXpn[NP * DF];
__device__ __align__(128) float g_fYpn[NP * DF];
__device__ __align__(128) float g_W[NX * DX];
__device__ __align__(128) float g_T[NX * DY];
__device__ __align__(128) float g_Sxx[DX * DX];
__device__ __align__(128) float g_Syy[DY * DY];
__device__ __align__(128) float g_Sxy[DX * DY];
__device__ __align__(128) float g_Gxx[DX * DX];
__device__ __align__(128) float g_Gyy[DY * DY];
__device__ __align__(128) float g_Gfx[DF * DF];
__device__ __align__(128) float g_Gfy[DF * DF];
__device__ __align__(128) float g_Gxf[DX * DF];
__device__ __align__(128) float g_Gfyy[DF * DY];
__device__ __align__(128) float g_U1[DX * DY];
__device__ __align__(128) float g_V1[DX * DY];
__device__ __align__(128) float g_W1[DX * DY];
__device__ __align__(128) float g_Ag[DX * DX];
__device__ __align__(128) float g_Bg[DY * DY];
__device__ __align__(128) float g_Gg[DX * DY];
__device__ float g_up[NP], g_vp[NP];
__device__ float g_uu[NX], g_vu[NX];
__device__ float g_ua[NX], g_va[NX];
__device__ float g_arow[NX], g_bcol[NX];
__device__ float g_ap[NP], g_bp[NP];
__device__ __align__(128) float g_ps[16 * NX];
__device__ double g_acc[16];

// ---------------------------------------------------------------------------
// Reduction helpers
// ---------------------------------------------------------------------------
__device__ __forceinline__ float warpSum(float v) {
    #pragma unroll
    for (int o = 16; o; o >>= 1) v += __shfl_xor_sync(0xffffffffu, v, o);
    return v;
}
__device__ __forceinline__ double warpSumD(double v) {
    #pragma unroll
    for (int o = 16; o; o >>= 1) v += __shfl_xor_sync(0xffffffffu, v, o);
    return v;
}
__device__ float blockSum(float v) {
    __shared__ float s[32];
    __syncthreads();
    int lane = threadIdx.x & 31, wid = threadIdx.x >> 5;
    v = warpSum(v);
    if (lane == 0) s[wid] = v;
    __syncthreads();
    if (wid == 0) {
        int nw = blockDim.x >> 5;
        v = (lane < nw) ? s[lane] : 0.f;
        v = warpSum(v);
    }
    return v;
}
__device__ double blockSumD(double v) {
    __shared__ double s[32];
    __syncthreads();
    int lane = threadIdx.x & 31, wid = threadIdx.x >> 5;
    v = warpSumD(v);
    if (lane == 0) s[wid] = v;
    __syncthreads();
    if (wid == 0) {
        int nw = blockDim.x >> 5;
        v = (lane < nw) ? s[lane] : 0.0;
        v = warpSumD(v);
    }
    return v;
}

// ---------------------------------------------------------------------------
// Tensor-core GEMM with split-bf16 (bf16x3) emulated fp32 + reg prefetch.
// C[M,N] = alpha * sum_k opA(m,k)*opB(k,n)
// TA=0: A row-major MxK ; TA=1: A row-major KxM (A^T)
// TB=0: B row-major KxN ; TB=1: B row-major NxK (B^T)
// Requires: M,N % 128 == 0, K % 16 == 0, lds % 4 == 0.
// ---------------------------------------------------------------------------
#define ASTRIDE 24

__device__ __forceinline__ void bsplit(float x, __nv_bfloat16& h, __nv_bfloat16& l) {
    h = __float2bfloat16(x);
    l = __float2bfloat16(x - __bfloat162float(h));
}
__device__ __forceinline__ uint32_t bpack(__nv_bfloat16 a, __nv_bfloat16 b) {
    __nv_bfloat162 t; t.x = a; t.y = b;
    return *reinterpret_cast<uint32_t*>(&t);
}
__device__ __forceinline__ void mma16816(float* c, const uint32_t* a, const uint32_t* b) {
    asm volatile(
        "mma.sync.aligned.m16n8k16.row.col.f32.bf16.bf16.f32 "
        "{%0,%1,%2,%3}, {%4,%5,%6,%7}, {%8,%9}, {%0,%1,%2,%3};\n"
        : "+f"(c[0]), "+f"(c[1]), "+f"(c[2]), "+f"(c[3])
        : "r"(a[0]), "r"(a[1]), "r"(a[2]), "r"(a[3]), "r"(b[0]), "r"(b[1]));
}

template <int TA, int TB>
__global__ __launch_bounds__(256, 2)
void gemm_mma_kernel(const float* __restrict__ A, const float* __restrict__ B,
                     float* __restrict__ C, int K,
                     int lda, int ldb, int ldc, float alpha) {
    __shared__ __align__(16) __nv_bfloat16 Ash[128][ASTRIDE];
    __shared__ __align__(16) __nv_bfloat16 Asl[128][ASTRIDE];
    __shared__ __align__(16) __nv_bfloat16 Bsh[128][ASTRIDE];
    __shared__ __align__(16) __nv_bfloat16 Bsl[128][ASTRIDE];

    const int tid = threadIdx.x;
    const int warp = tid >> 5, lane = tid & 31;
    const int bm = blockIdx.y * 128, bn = blockIdx.x * 128;
    const int wm = (warp >> 2) * 64;
    const int wn = (warp & 3) * 32;

    float acc[4][4][4];
    #pragma unroll
    for (int mi = 0; mi < 4; mi++)
        #pragma unroll
        for (int ni = 0; ni < 4; ni++)
            #pragma unroll
            for (int e = 0; e < 4; e++) acc[mi][ni][e] = 0.f;

    float4 va[2], vb[2];

    auto load_tiles = [&](int k0) {
        #pragma unroll
        for (int i = 0; i < 2; i++) {
            int f = tid * 2 + i;
            if (TA == 0) {
                int row = f >> 2, c4 = (f & 3) * 4;
                va[i] = *(const float4*)&A[(size_t)(bm + row) * lda + k0 + c4];
            } else {
                int kr = f >> 5, m0 = (f & 31) * 4;
                va[i] = *(const float4*)&A[(size_t)(k0 + kr) * lda + bm + m0];
            }
            if (TB == 1) {
                int row = f >> 2, c4 = (f & 3) * 4;
                vb[i] = *(const float4*)&B[(size_t)(bn + row) * ldb + k0 + c4];
            } else {
                int kr = f >> 5, n0 = (f & 31) * 4;
                vb[i] = *(const float4*)&B[(size_t)(k0 + kr) * ldb + bn + n0];
            }
        }
    };
    auto stage_tiles = [&]() {
        #pragma unroll
        for (int i = 0; i < 2; i++) {
            int f = tid * 2 + i;
            float4 v = va[i];
            if (TA == 0) {
                int row = f >> 2, c4 = (f & 3) * 4;
                __nv_bfloat16 h0, h1, h2, h3, l0, l1, l2, l3;
                bsplit(v.x, h0, l0); bsplit(v.y, h1, l1);
                bsplit(v.z, h2, l2); bsplit(v.w, h3, l3);
                *(uint2*)&Ash[row][c4] = make_uint2(bpack(h0, h1), bpack(h2, h3));
                *(uint2*)&Asl[row][c4] = make_uint2(bpack(l0, l1), bpack(l2, l3));
            } else {
                int kr = f >> 5, m0 = (f & 31) * 4;
                __nv_bfloat16 h, l;
                bsplit(v.x, h, l); Ash[m0 + 0][kr] = h; Asl[m0 + 0][kr] = l;
                bsplit(v.y, h, l); Ash[m0 + 1][kr] = h; Asl[m0 + 1][kr] = l;
                bsplit(v.z, h, l); Ash[m0 + 2][kr] = h; Asl[m0 + 2][kr] = l;
                bsplit(v.w, h, l); Ash[m0 + 3][kr] = h; Asl[m0 + 3][kr] = l;
            }
            v = vb[i];
            if (TB == 1) {
                int row = f >> 2, c4 = (f & 3) * 4;
                __nv_bfloat16 h0, h1, h2, h3, l0, l1, l2, l3;
                bsplit(v.x, h0, l0); bsplit(v.y, h1, l1);
                bsplit(v.z, h2, l2); bsplit(v.w, h3, l3);
                *(uint2*)&Bsh[row][c4] = make_uint2(bpack(h0, h1), bpack(h2, h3));
                *(uint2*)&Bsl[row][c4] = make_uint2(bpack(l0, l1), bpack(l2, l3));
            } else {
                int kr = f >> 5, n0 = (f & 31) * 4;
                __nv_bfloat16 h, l;
                bsplit(v.x, h, l); Bsh[n0 + 0][kr] = h; Bsl[n0 + 0][kr] = l;
                bsplit(v.y, h, l); Bsh[n0 + 1][kr] = h; Bsl[n0 + 1][kr] = l;
                bsplit(v.z, h, l); Bsh[n0 + 2][kr] = h; Bsl[n0 + 2][kr] = l;
                bsplit(v.w, h, l); Bsh[n0 + 3][kr] = h; Bsl[n0 + 3][kr] = l;
            }
        }
    };

    load_tiles(0);
    for (int k0 = 0; k0 < K; k0 += 16) {
        __syncthreads();
        stage_tiles();
        __syncthreads();
        if (k0 + 16 < K) load_tiles(k0 + 16);

        const int fr = lane >> 2;
        const int fc = (lane & 3) * 2;
        uint32_t bh[4][2], bl[4][2];
        #pragma unroll
        for (int ni = 0; ni < 4; ni++) {
            int nr = wn + ni * 8 + fr;
            bh[ni][0] = *(const uint32_t*)&Bsh[nr][fc];
            bh[ni][1] = *(const uint32_t*)&Bsh[nr][fc + 8];
            bl[ni][0] = *(const uint32_t*)&Bsl[nr][fc];
            bl[ni][1] = *(const uint32_t*)&Bsl[nr][fc + 8];
        }
        #pragma unroll
        for (int mi = 0; mi < 4; mi++) {
            int r0 = wm + mi * 16 + fr;
            uint32_t ah[4], al[4];
            ah[0] = *(const uint32_t*)&Ash[r0][fc];
            ah[1] = *(const uint32_t*)&Ash[r0 + 8][fc];
            ah[2] = *(const uint32_t*)&Ash[r0][fc + 8];
            ah[3] = *(const uint32_t*)&Ash[r0 + 8][fc + 8];
            al[0] = *(const uint32_t*)&Asl[r0][fc];
            al[1] = *(const uint32_t*)&Asl[r0 + 8][fc];
            al[2] = *(const uint32_t*)&Asl[r0][fc + 8];
            al[3] = *(const uint32_t*)&Asl[r0 + 8][fc + 8];
            #pragma unroll
            for (int ni = 0; ni < 4; ni++) {
                mma16816(acc[mi][ni], ah, bh[ni]);
                mma16816(acc[mi][ni], ah, bl[ni]);
                mma16816(acc[mi][ni], al, bh[ni]);
            }
        }
    }

    const int fr = lane >> 2;
    const int fc = (lane & 3) * 2;
    #pragma unroll
    for (int mi = 0; mi < 4; mi++) {
        int r = bm + wm + mi * 16 + fr;
        #pragma unroll
        for (int ni = 0; ni < 4; ni++) {
            int c = bn + wn + ni * 8 + fc;
            float2 v0, v1;
            v0.x = alpha * acc[mi][ni][0];
            v0.y = alpha * acc[mi][ni][1];
            v1.x = alpha * acc[mi][ni][2];
            v1.y = alpha * acc[mi][ni][3];
            *(float2*)&C[(size_t)r * ldc + c] = v0;
            *(float2*)&C[(size_t)(r + 8) * ldc + c] = v1;
        }
    }
}

// ---------------------------------------------------------------------------
// Elementwise / reduction kernels
// ---------------------------------------------------------------------------
__global__ void zero_acc_kernel(double* a) { if (threadIdx.x < 16) a[threadIdx.x] = 0.0; }
__global__ void zero_vec_kernel(float* p, int n) {
    int i = blockIdx.x * blockDim.x + threadIdx.x;
    if (i < n) p[i] = 0.f;
}

__global__ void rownorm_kernel(const float* __restrict__ in, float* __restrict__ out, int D) {
    int row = blockIdx.x;
    const float* r = in + (size_t)row * D;
    float ss = 0.f;
    for (int i = threadIdx.x * 4; i < D; i += blockDim.x * 4) {
        float4 v = *(const float4*)&r[i];
        ss += v.x * v.x + v.y * v.y + v.z * v.z + v.w * v.w;
    }
    ss = blockSum(ss);
    __shared__ float s_inv;
    if (threadIdx.x == 0) s_inv = 1.f / fmaxf(sqrtf(ss), 1e-8f);
    __syncthreads();
    float inv = s_inv;
    for (int i = threadIdx.x * 4; i < D; i += blockDim.x * 4) {
        float4 v = *(const float4*)&r[i];
        v.x *= inv; v.y *= inv; v.z *= inv; v.w *= inv;
        *(float4*)&out[(size_t)row * D + i] = v;
    }
}

__global__ void quadnorm_kernel(const float* __restrict__ X, const float* __restrict__ W,
                                float* __restrict__ out, int D) {
    int row = blockIdx.x;
    const float* xr = X + (size_t)row * D;
    const float* wr = W + (size_t)row * D;
    float ss = 0.f;
    for (int i = threadIdx.x * 4; i < D; i += blockDim.x * 4) {
        float4 a = *(const float4*)&xr[i];
        float4 b = *(const float4*)&wr[i];
        ss += a.x * b.x + a.y * b.y + a.z * b.z + a.w * b.w;
    }
    ss = blockSum(ss);
    __shared__ float s_inv;
    if (threadIdx.x == 0) s_inv = 1.f / fmaxf(sqrtf(ss), 1e-8f);
    __syncthreads();
    float inv = s_inv;
    for (int i = threadIdx.x * 4; i < D; i += blockDim.x * 4) {
        float4 v = *(const float4*)&xr[i];
        v.x *= inv; v.y *= inv; v.z *= inv; v.w *= inv;
        *(float4*)&out[(size_t)row * D + i] = v;
    }
}

__global__ void scale_rows_sqrt_kernel(const float* __restrict__ X, const float* __restrict__ a,
                                       float* __restrict__ out, int D) {
    int row = blockIdx.x;
    float sc = sqrtf(fmaxf(a[row], 0.f));
    for (int i = threadIdx.x * 4; i < D; i += blockDim.x * 4) {
        float4 v = *(const float4*)&X[(size_t)row * D + i];
        v.x *= sc; v.y *= sc; v.z *= sc; v.w *= sc;
        *(float4*)&out[(size_t)row * D + i] = v;
    }
}

// u[row] = log_a - log(sum_c exp(M+v)) ; no-max LSE with constant shift LSE_C
__global__ void row_sumexp_kernel(const float* __restrict__ M, const float* __restrict__ v,
                                  float* __restrict__ u, int ny, float log_a) {
    int row = blockIdx.x;
    const float* Mr = M + (size_t)row * ny;
    float s = 0.f;
    for (int c = threadIdx.x * 4; c < ny; c += blockDim.x * 4) {
        float4 m = *(const float4*)&Mr[c];
        float4 vv = *(const float4*)&v[c];
        s += __expf(m.x + vv.x - LSE_C) + __expf(m.y + vv.y - LSE_C)
           + __expf(m.z + vv.z - LSE_C) + __expf(m.w + vv.w - LSE_C);
    }
    s = blockSum(s);
    if (threadIdx.x == 0) u[row] = log_a - (LSE_C + __logf(s));
}

__global__ void col_sumexp_partial_kernel(const float* __restrict__ M, const float* __restrict__ u,
                                          float* __restrict__ ps, int nx, int ny, int chunk) {
    int col = blockIdx.x * blockDim.x + threadIdx.x;
    int r0 = blockIdx.y * chunk;
    int r1 = min(r0 + chunk, nx);
    float s = 0.f;
    for (int r = r0; r < r1; r += 4) {
        float x0 = M[(size_t)r * ny + col] + __ldg(&u[r]);
        float x1 = M[(size_t)(r + 1) * ny + col] + __ldg(&u[r + 1]);
        float x2 = M[(size_t)(r + 2) * ny + col] + __ldg(&u[r + 2]);
        float x3 = M[(size_t)(r + 3) * ny + col] + __ldg(&u[r + 3]);
        s += __expf(x0 - LSE_C) + __expf(x1 - LSE_C)
           + __expf(x2 - LSE_C) + __expf(x3 - LSE_C);
    }
    ps[(size_t)blockIdx.y * ny + col] = s;
}

__global__ void col_combine_kernel(const float* __restrict__ ps, float* __restrict__ v,
                                   int ny, int nch, float log_b) {
    int col = blockIdx.x * blockDim.x + threadIdx.x;
    float s = 0.f;
    for (int c = 0; c < nch; c++) s += ps[(size_t)c * ny + col];
    v[col] = log_b - (LSE_C + __logf(s));
}

__global__ void plan_rowsum_kernel(const float* __restrict__ M, const float* __restrict__ u,
                                   const float* __restrict__ v, float* __restrict__ rowsum,
                                   float* __restrict__ P, int ny) {
    int row = blockIdx.x;
    float uv = u[row];
    const float* Mr = M + (size_t)row * ny;
    float s = 0.f;
    for (int c = threadIdx.x * 4; c < ny; c += blockDim.x * 4) {
        float4 m = *(const float4*)&Mr[c];
        float4 vv = *(const float4*)&v[c];
        float4 p;
        p.x = __expf(m.x + uv + vv.x);
        p.y = __expf(m.y + uv + vv.y);
        p.z = __expf(m.z + uv + vv.z);
        p.w = __expf(m.w + uv + vv.w);
        if (P) *(float4*)&P[(size_t)row * ny + c] = p;
        s += p.x + p.y + p.z + p.w;
    }
    s = blockSum(s);
    if (threadIdx.x == 0) rowsum[row] = s;
}

__global__ void plan_colsum_partial_kernel(const float* __restrict__ M, const float* __restrict__ u,
                                           const float* __restrict__ v, float* __restrict__ ps,
                                           int nx, int ny, int chunk) {
    int col = blockIdx.x * blockDim.x + threadIdx.x;
    int r0 = blockIdx.y * chunk;
    int r1 = min(r0 + chunk, nx);
    float vc = v[col];
    float s = 0.f;
    for (int r = r0; r < r1; r += 4) {
        float x0 = M[(size_t)r * ny + col] + __ldg(&u[r]);
        float x1 = M[(size_t)(r + 1) * ny + col] + __ldg(&u[r + 1]);
        float x2 = M[(size_t)(r + 2) * ny + col] + __ldg(&u[r + 2]);
        float x3 = M[(size_t)(r + 3) * ny + col] + __ldg(&u[r + 3]);
        s += __expf(x0 + vc) + __expf(x1 + vc) + __expf(x2 + vc) + __expf(x3 + vc);
    }
    ps[(size_t)blockIdx.y * ny + col] = s;
}

__global__ void colsum_combine_kernel(const float* __restrict__ ps, float* __restrict__ b,
                                      int ny, int nch) {
    int col = blockIdx.x * blockDim.x + threadIdx.x;
    float s = 0.f;
    for (int c = 0; c < nch; c++) s += ps[(size_t)c * ny + col];
    b[col] = s;
}

__global__ void marg_acc_kernel(const float* __restrict__ sums, int n, double* acc) {
    int i = blockIdx.x * blockDim.x + threadIdx.x;
    double t = 0.0;
    if (i < n) {
        float d = sums[i] - 1.f / (float)n;
        t = (double)d * (double)d;
    }
    t = blockSumD(t);
    if (threadIdx.x == 0) atomicAdd(&acc[S_MARG], t);
}

// SAIL: sum softplus(-z), z = Mp*0.5*target ; n power of two, shift = log2(n)
__global__ void sail_acc_kernel(const float* __restrict__ Mp, int n, int shift, double* acc) {
    size_t total4 = ((size_t)n * n) >> 2;
    double t = 0.0;
    for (size_t i4 = (size_t)blockIdx.x * blockDim.x + threadIdx.x; i4 < total4;
         i4 += (size_t)gridDim.x * blockDim.x) {
        size_t base = i4 * 4;
        int i = (int)(base >> shift);
        int j = (int)(base & (size_t)(n - 1));
        float4 m = *(const float4*)&Mp[base];
        float mv[4] = {m.x, m.y, m.z, m.w};
        float acc4 = 0.f;
        #pragma unroll
        for (int k = 0; k < 4; k++) {
            float z = mv[k] * 0.5f;
            if (j + k != i) z = -z;
            float a = -z;
            acc4 += fmaxf(a, 0.f) + log1pf(__expf(-fabsf(a)));
        }
        t += (double)acc4;
    }
    t = blockSumD(t);
    if (threadIdx.x == 0) atomicAdd(&acc[S_SAIL], t);
}

__global__ void diag_acc_kernel(const float* __restrict__ Mp, const float* __restrict__ u,
                                const float* __restrict__ v, int n, float logN, double* acc) {
    int i = blockIdx.x * blockDim.x + threadIdx.x;
    double ti = 0.0, te = 0.0;
    if (i < n) {
        float mii = Mp[(size_t)i * n + i];
        ti = (double)(mii + u[i] + v[i] + logN);
        te = (double)((1.f - mii * 0.05f) * 0.5f);
    }
    ti = blockSumD(ti);
    __shared__ double sh;
    if (threadIdx.x == 0) sh = ti;
    te = blockSumD(te);
    if (threadIdx.x == 0) {
        atomicAdd(&acc[S_IMP], sh);
        atomicAdd(&acc[S_EXP], te);
    }
}

// L_ot = sum exp(la) * (la - lu) ; n power of two, shift = log2(n)
__global__ void ot_acc_kernel(const float* __restrict__ Ca, const float* __restrict__ Mu,
                              const float* __restrict__ ua, const float* __restrict__ va,
                              const float* __restrict__ uu, const float* __restrict__ vu,
                              int n, int shift, double* acc) {
    size_t total4 = ((size_t)n * n) >> 2;
    double t = 0.0;
    for (size_t i4 = (size_t)blockIdx.x * blockDim.x + threadIdx.x; i4 < total4;
         i4 += (size_t)gridDim.x * blockDim.x) {
        size_t base = i4 * 4;
        int i = (int)(base >> shift);
        int j = (int)(base & (size_t)(n - 1));
        float4 a4 = *(const float4*)&Ca[base];
        float4 m4 = *(const float4*)&Mu[base];
        float4 vaj = *(const float4*)&va[j];
        float4 vuj = *(const float4*)&vu[j];
        float uai = __ldg(&ua[i]), uui = __ldg(&uu[i]);
        float la, lu, s = 0.f;
        la = a4.x + uai + vaj.x; lu = m4.x + uui + vuj.x; s += __expf(la) * (la - lu);
        la = a4.y + uai + vaj.y; lu = m4.y + uui + vuj.y; s += __expf(la) * (la - lu);
        la = a4.z + uai + vaj.z; lu = m4.z + uui + vuj.z; s += __expf(la) * (la - lu);
        la = a4.w + uai + vaj.w; lu = m4.w + uui + vuj.w; s += __expf(la) * (la - lu);
        t += (double)s;
    }
    t = blockSumD(t);
    if (threadIdx.x == 0) atomicAdd(&acc[S_OT], t);
}

__global__ void dot_acc_kernel(const float* __restrict__ A, const float* __restrict__ B,
                               int n, double* acc, int slot) {
    double t = 0.0;
    for (int i = blockIdx.x * blockDim.x + threadIdx.x; i < n; i += gridDim.x * blockDim.x)
        t += (double)A[i] * (double)B[i];
    t = blockSumD(t);
    if (threadIdx.x == 0) atomicAdd(&acc[slot], t);
}

__global__ void sumsq_acc_kernel(const float* __restrict__ A, int n, double* acc, int slot) {
    double t = 0.0;
    for (int i = blockIdx.x * blockDim.x + threadIdx.x; i < n; i += gridDim.x * blockDim.x)
        t += (double)A[i] * (double)A[i];
    t = blockSumD(t);
    if (threadIdx.x == 0) atomicAdd(&acc[slot], t);
}

__global__ void finalize_kernel(const double* __restrict__ acc, float* __restrict__ out) {
    double L = acc[S_MARG]
             + acc[S_SAIL] / ((double)NP * (double)NP)
             + acc[S_EXP] / (double)NP
             - acc[S_IMP] / (double)NP
             + acc[S_OT]
             + (acc[S_N1] + acc[S_N2] - 2.0 * acc[S_DT]) / ((double)NX * (double)NX)
             + (acc[S_SQA] + acc[S_SQB] - 2.0 * acc[S_SQG]);
    out[0] = (float)L;
}

// ---------------------------------------------------------------------------
// Host side
// ---------------------------------------------------------------------------
static inline void launch_gemm(int TA, int TB, const float* A, const float* B, float* C,
                               int M, int N, int K, int lda, int ldb, int ldc, float alpha) {
    dim3 grid(N / 128, M / 128), block(256);
    if (TA == 0 && TB == 0) gemm_mma_kernel<0, 0><<<grid, block>>>(A, B, C, K, lda, ldb, ldc, alpha);
    else if (TA == 0 && TB == 1) gemm_mma_kernel<0, 1><<<grid, block>>>(A, B, C, K, lda, ldb, ldc, alpha);
    else gemm_mma_kernel<1, 0><<<grid, block>>>(A, B, C, K, lda, ldb, ldc, alpha);
}

static void run_sinkhorn(float* M, float* u, float* v, int nx, int ny, float* ps) {
    float log_a = -logf((float)nx), log_b = -logf((float)ny);
    const int CH = 256;
    int nch = nx / CH;
    zero_vec_kernel<<<(ny + 255) / 256, 256>>>(v, ny);
    dim3 cgrid(ny / 256, nch);
    for (int it = 0; it < SINK_IT; it++) {
        row_sumexp_kernel<<<nx, 256>>>(M, v, u, ny, log_a);
        col_sumexp_partial_kernel<<<cgrid, 256>>>(M, u, ps, nx, ny, CH);
        col_combine_kernel<<<ny / 256, 256>>>(ps, v, ny, nch, log_b);
    }
}

#define GETSYM(ptr, sym) do { void* _t; cudaGetSymbolAddress(&_t, sym); ptr = (float*)_t; } while (0)

extern "C" void kernel_launch(void* const* d_in, const int* in_sizes, int n_in,
                              void* d_out, int out_size) {
    const float* fXp = (const float*)d_in[0];   // 2048x256
    const float* fYp = (const float*)d_in[1];   // 2048x256
    const float* X   = (const float*)d_in[2];   // 4096x768
    const float* Y   = (const float*)d_in[3];   // 4096x512
    const float* fX  = (const float*)d_in[4];   // 4096x256
    const float* fY  = (const float*)d_in[5];   // 4096x256
    const float* Xan = (const float*)d_in[6];   // 4096x768
    const float* Yan = (const float*)d_in[7];   // 4096x512
    float* out = (float*)d_out;

    float *Mp, *Mu, *Ca, *P, *Xa, *Ya, *Xu, *Yu, *Xn, *Yn, *fXn, *fYn, *fXpn, *fYpn;
    float *W, *T, *Sxx, *Syy, *Sxy, *Gxx, *Gyy, *Gfx, *Gfy, *Gxf, *Gfyy, *U1, *V1, *W1;
    float *Ag, *Bg, *Gg, *up, *vp, *uu, *vu, *ua, *va, *arow, *bcol, *ap, *bp, *ps;
    double* acc;
    GETSYM(Mp, g_Mp); GETSYM(Mu, g_Mu); GETSYM(Ca, g_Ca); GETSYM(P, g_P);
    GETSYM(Xa, g_Xa); GETSYM(Ya, g_Ya); GETSYM(Xu, g_Xu); GETSYM(Yu, g_Yu);
    GETSYM(Xn, g_Xn); GETSYM(Yn, g_Yn); GETSYM(fXn, g_fXn); GETSYM(fYn, g_fYn);
    GETSYM(fXpn, g_fXpn); GETSYM(fYpn, g_fYpn);
    GETSYM(W, g_W); GETSYM(T, g_T);
    GETSYM(Sxx, g_Sxx); GETSYM(Syy, g_Syy); GETSYM(Sxy, g_Sxy);
    GETSYM(Gxx, g_Gxx); GETSYM(Gyy, g_Gyy); GETSYM(Gfx, g_Gfx); GETSYM(Gfy, g_Gfy);
    GETSYM(Gxf, g_Gxf); GETSYM(Gfyy, g_Gfyy); GETSYM(U1, g_U1); GETSYM(V1, g_V1); GETSYM(W1, g_W1);
    GETSYM(Ag, g_Ag); GETSYM(Bg, g_Bg); GETSYM(Gg, g_Gg);
    GETSYM(up, g_up); GETSYM(vp, g_vp); GETSYM(uu, g_uu); GETSYM(vu, g_vu);
    GETSYM(ua, g_ua); GETSYM(va, g_va);
    GETSYM(arow, g_arow); GETSYM(bcol, g_bcol); GETSYM(ap, g_ap); GETSYM(bp, g_bp);
    GETSYM(ps, g_ps);
    { void* _t; cudaGetSymbolAddress(&_t, g_acc); acc = (double*)_t; }

    // Launch order note: launch #6 is the big Mu GEMM so ncu (-s 5 -c 1)
    // profiles it instead of a trivial rownorm.
    zero_acc_kernel<<<1, 32>>>(acc);               // 1
    rownorm_kernel<<<NX, 256>>>(fX, fXn, DF);      // 2
    rownorm_kernel<<<NX, 256>>>(fY, fYn, DF);      // 3
    rownorm_kernel<<<NX, 256>>>(Xan, Xa, DX);      // 4
    rownorm_kernel<<<NX, 256>>>(Yan, Ya, DY);      // 5
    launch_gemm(0, 1, fXn, fYn, Mu, NX, NX, DF, DF, DF, NX, EPS_INV);  // 6 <- profiled

    rownorm_kernel<<<NP, 256>>>(fXp, fXpn, DF);
    rownorm_kernel<<<NP, 256>>>(fYp, fYpn, DF);
    rownorm_kernel<<<NX, 256>>>(X, Xu, DX);
    rownorm_kernel<<<NX, 256>>>(Y, Yu, DY);

    // --- anchor covariances ---
    launch_gemm(1, 0, Xa, Xa, Sxx, DX, DX, NX, DX, DX, DX, 1.f / NX);
    launch_gemm(1, 0, Ya, Ya, Syy, DY, DY, NX, DY, DY, DY, 1.f / NX);
    launch_gemm(1, 0, Xa, Ya, Sxy, DX, DY, NX, DX, DY, DY, 1.f / NX);

    // --- pairs cosine matrix ---
    launch_gemm(0, 1, fXpn, fYpn, Mp, NP, NP, DF, DF, DF, NP, EPS_INV);

    // --- shared-space sinkhorns ---
    run_sinkhorn(Mp, up, vp, NP, NP, ps);
    run_sinkhorn(Mu, uu, vu, NX, NX, ps);

    // --- pairs plan stats ---
    plan_rowsum_kernel<<<NP, 256>>>(Mp, up, vp, ap, nullptr, NP);
    plan_colsum_partial_kernel<<<dim3(NP / 256, NP / 256), 256>>>(Mp, up, vp, ps, NP, NP, 256);
    colsum_combine_kernel<<<NP / 256, 256>>>(ps, bp, NP, NP / 256);
    marg_acc_kernel<<<NP / 256, 256>>>(ap, NP, acc);
    marg_acc_kernel<<<NP / 256, 256>>>(bp, NP, acc);
    sail_acc_kernel<<<1024, 256>>>(Mp, NP, 11, acc);
    diag_acc_kernel<<<NP / 256, 256>>>(Mp, up, vp, NP, logf((float)NP), acc);

    // --- latent plan stats (and materialize plan_u) ---
    plan_rowsum_kernel<<<NX, 256>>>(Mu, uu, vu, arow, P, NX);
    plan_colsum_partial_kernel<<<dim3(NX / 256, NX / 256), 256>>>(Mu, uu, vu, ps, NX, NX, 256);
    colsum_combine_kernel<<<NX / 256, 256>>>(ps, bcol, NX, NX / 256);
    marg_acc_kernel<<<NX / 256, 256>>>(arow, NX, acc);
    marg_acc_kernel<<<NX / 256, 256>>>(bcol, NX, acc);

    // --- anchor-space normalization + plan ---
    launch_gemm(0, 0, X, Sxx, W, NX, DX, DX, DX, DX, DX, 1.f);
    quadnorm_kernel<<<NX, 256>>>(X, W, Xn, DX);
    launch_gemm(0, 0, Y, Syy, W, NX, DY, DY, DY, DY, DY, 1.f);
    quadnorm_kernel<<<NX, 256>>>(Y, W, Yn, DY);
    launch_gemm(0, 0, Xn, Sxy, T, NX, DY, DX, DX, DY, DY, 1.f);
    launch_gemm(0, 1, T, Yn, Ca, NX, NX, DY, DY, DY, NX, EPS_INV);
    run_sinkhorn(Ca, ua, va, NX, NX, ps);

    // --- L_ot ---
    ot_acc_kernel<<<2048, 256>>>(Ca, Mu, ua, va, uu, vu, NX, 12, acc);

    // --- L_div ---
    launch_gemm(1, 0, Xn, Xn, Gxx, DX, DX, NX, DX, DX, DX, 1.f);
    launch_gemm(1, 0, Yn, Yn, Gyy, DY, DY, NX, DY, DY, DY, 1.f);
    launch_gemm(1, 0, fXn, fXn, Gfx, DF, DF, NX, DF, DF, DF, 1.f);
    launch_gemm(1, 0, fYn, fYn, Gfy, DF, DF, NX, DF, DF, DF, 1.f);
    launch_gemm(1, 0, Xn, fXn, Gxf, DX, DF, NX, DX, DF, DF, 1.f);
    launch_gemm(1, 0, fYn, Yn, Gfyy, DF, DY, NX, DF, DY, DY, 1.f);
    launch_gemm(0, 0, Gxx, Sxy, U1, DX, DY, DX, DX, DY, DY, 1.f);
    launch_gemm(0, 0, U1, Gyy, V1, DX, DY, DY, DY, DY, DY, 1.f);
    launch_gemm(0, 0, Gxf, Gfyy, W1, DX, DY, DF, DF, DY, DY, 1.f);
    dot_acc_kernel<<<256, 256>>>(V1, Sxy, DX * DY, acc, S_N1);
    dot_acc_kernel<<<256, 256>>>(Gfx, Gfy, DF * DF, acc, S_N2);
    dot_acc_kernel<<<256, 256>>>(W1, Sxy, DX * DY, acc, S_DT);

    // --- L_gw ---
    scale_rows_sqrt_kernel<<<NX, 256>>>(Xu, arow, W, DX);
    launch_gemm(1, 0, W, W, Ag, DX, DX, NX, DX, DX, DX, 1.f);
    sumsq_acc_kernel<<<256, 256>>>(Ag, DX * DX, acc, S_SQA);
    scale_rows_sqrt_kernel<<<NX, 256>>>(Yu, bcol, W, DY);
    launch_gemm(1, 0, W, W, Bg, DY, DY, NX, DY, DY, DY, 1.f);
    sumsq_acc_kernel<<<256, 256>>>(Bg, DY * DY, acc, S_SQB);
    launch_gemm(0, 0, P, Yu, T, NX, DY, NX, NX, DY, DY, 1.f);   // PY = plan_u @ Yu
    launch_gemm(1, 0, Xu, T, Gg, DX, DY, NX, DX, DY, DY, 1.f);  // G = Xu^T @ PY
    sumsq_acc_kernel<<<256, 256>>>(Gg, DX * DY, acc, S_SQG);

    finalize_kernel<<<1, 1>>>(acc, out);
}

// round 8
// speedup vs baseline: 1.1835x; 1.0180x over previous
#include <cuda_runtime.h>
#include <cuda_bf16.h>
#include <math.h>
#include <stdint.h>

// ---------------------------------------------------------------------------
// Problem dims (fixed by the dataset)
// ---------------------------------------------------------------------------
#define NP 2048   // pairs
#define NX 4096   // X/Y rows
#define DX 768    // X dim
#define DY 512    // Y dim
#define DF 256    // feature dim
#define EPS_INV 20.0f   // 1/0.05
#define SINK_IT 10
#define LSE_C 20.0f     // constant shift: |M| <= 20 provably

// acc slots
#define S_MARG 0
#define S_SAIL 1
#define S_EXP  2
#define S_IMP  3
#define S_OT   4
#define S_N1   5
#define S_N2   6
#define S_DT   7
#define S_SQA  8
#define S_SQB  9
#define S_SQG  10

// ---------------------------------------------------------------------------
// Static device scratch (no allocations allowed)
// ---------------------------------------------------------------------------
__device__ __align__(128) float g_Mp[(size_t)NP * NP];   // log kernel (pairs)
__device__ __align__(128) float g_Kp[(size_t)NP * NP];   // exp kernel (pairs)
__device__ __align__(128) float g_Mu[(size_t)NX * NX];   // log kernel (latent)
__device__ __align__(128) float g_Ku[(size_t)NX * NX];   // exp kernel (latent)
__device__ __align__(128) float g_Ca[(size_t)NX * NX];   // log kernel (anchor)
__device__ __align__(128) float g_Ka[(size_t)NX * NX];   // exp kernel (anchor)
__device__ __align__(128) float g_Xa[NX * DX];
__device__ __align__(128) float g_Ya[NX * DY];
__device__ __align__(128) float g_Xu[NX * DX];
__device__ __align__(128) float g_Yu[NX * DY];
__device__ __align__(128) float g_Xn[NX * DX];
__device__ __align__(128) float g_Yn[NX * DY];
__device__ __align__(128) float g_fXn[NX * DF];
__device__ __align__(128) float g_fYn[NX * DF];
__device__ __align__(128) float g_fXpn[NP * DF];
__device__ __align__(128) float g_fYpn[NP * DF];
__device__ __align__(128) float g_W[NX * DX];
__device__ __align__(128) float g_T[NX * DY];
__device__ __align__(128) float g_Sxx[DX * DX];
__device__ __align__(128) float g_Syy[DY * DY];
__device__ __align__(128) float g_Sxy[DX * DY];
__device__ __align__(128) float g_Gxx[DX * DX];
__device__ __align__(128) float g_Gyy[DY * DY];
__device__ __align__(128) float g_Gfx[DF * DF];
__device__ __align__(128) float g_Gfy[DF * DF];
__device__ __align__(128) float g_Gxf[DX * DF];
__device__ __align__(128) float g_Gfyy[DF * DY];
__device__ __align__(128) float g_U1[DX * DY];
__device__ __align__(128) float g_V1[DX * DY];
__device__ __align__(128) float g_W1[DX * DY];
__device__ __align__(128) float g_Ag[DX * DX];
__device__ __align__(128) float g_Bg[DY * DY];
__device__ __align__(128) float g_Gg[DX * DY];
// scaling-domain potentials (positive scalings)
__device__ __align__(16) float g_up[NP], g_wp[NP];
__device__ __align__(16) float g_uu[NX], g_wu[NX];
__device__ __align__(16) float g_ua[NX], g_wa[NX];
__device__ __align__(16) float g_arow[NX], g_bcol[NX];
__device__ __align__(16) float g_ap[NP], g_bp[NP];
__device__ __align__(16) float g_dvec[NX], g_evec[NX];
__device__ __align__(128) float g_ps[16 * NX];
__device__ double g_acc[16];

// ---------------------------------------------------------------------------
// Reduction helpers
// ---------------------------------------------------------------------------
__device__ __forceinline__ float warpSum(float v) {
    #pragma unroll
    for (int o = 16; o; o >>= 1) v += __shfl_xor_sync(0xffffffffu, v, o);
    return v;
}
__device__ __forceinline__ double warpSumD(double v) {
    #pragma unroll
    for (int o = 16; o; o >>= 1) v += __shfl_xor_sync(0xffffffffu, v, o);
    return v;
}
__device__ float blockSum(float v) {
    __shared__ float s[32];
    __syncthreads();
    int lane = threadIdx.x & 31, wid = threadIdx.x >> 5;
    v = warpSum(v);
    if (lane == 0) s[wid] = v;
    __syncthreads();
    if (wid == 0) {
        int nw = blockDim.x >> 5;
        v = (lane < nw) ? s[lane] : 0.f;
        v = warpSum(v);
    }
    return v;
}
__device__ double blockSumD(double v) {
    __shared__ double s[32];
    __syncthreads();
    int lane = threadIdx.x & 31, wid = threadIdx.x >> 5;
    v = warpSumD(v);
    if (lane == 0) s[wid] = v;
    __syncthreads();
    if (wid == 0) {
        int nw = blockDim.x >> 5;
        v = (lane < nw) ? s[lane] : 0.0;
        v = warpSumD(v);
    }
    return v;
}

// ---------------------------------------------------------------------------
// Tensor-core GEMM with split-bf16 (bf16x3) emulated fp32 + reg prefetch.
// C = alpha * opA @ opB ; optional Kout = exp(C - LSE_C) epilogue.
// TA=0: A row-major MxK ; TA=1: A row-major KxM (A^T)
// TB=0: B row-major KxN ; TB=1: B row-major NxK (B^T)
// Requires: M,N % 128 == 0, K % 16 == 0.
// ---------------------------------------------------------------------------
#define ASTRIDE 24

__device__ __forceinline__ void bsplit(float x, __nv_bfloat16& h, __nv_bfloat16& l) {
    h = __float2bfloat16(x);
    l = __float2bfloat16(x - __bfloat162float(h));
}
__device__ __forceinline__ uint32_t bpack(__nv_bfloat16 a, __nv_bfloat16 b) {
    __nv_bfloat162 t; t.x = a; t.y = b;
    return *reinterpret_cast<uint32_t*>(&t);
}
__device__ __forceinline__ void mma16816(float* c, const uint32_t* a, const uint32_t* b) {
    asm volatile(
        "mma.sync.aligned.m16n8k16.row.col.f32.bf16.bf16.f32 "
        "{%0,%1,%2,%3}, {%4,%5,%6,%7}, {%8,%9}, {%0,%1,%2,%3};\n"
        : "+f"(c[0]), "+f"(c[1]), "+f"(c[2]), "+f"(c[3])
        : "r"(a[0]), "r"(a[1]), "r"(a[2]), "r"(a[3]), "r"(b[0]), "r"(b[1]));
}

template <int TA, int TB>
__global__ __launch_bounds__(256, 2)
void gemm_mma_kernel(const float* __restrict__ A, const float* __restrict__ B,
                     float* __restrict__ C, float* __restrict__ Kout, int K,
                     int lda, int ldb, int ldc, float alpha) {
    __shared__ __align__(16) __nv_bfloat16 Ash[128][ASTRIDE];
    __shared__ __align__(16) __nv_bfloat16 Asl[128][ASTRIDE];
    __shared__ __align__(16) __nv_bfloat16 Bsh[128][ASTRIDE];
    __shared__ __align__(16) __nv_bfloat16 Bsl[128][ASTRIDE];

    const int tid = threadIdx.x;
    const int warp = tid >> 5, lane = tid & 31;
    const int bm = blockIdx.y * 128, bn = blockIdx.x * 128;
    const int wm = (warp >> 2) * 64;
    const int wn = (warp & 3) * 32;

    float acc[4][4][4];
    #pragma unroll
    for (int mi = 0; mi < 4; mi++)
        #pragma unroll
        for (int ni = 0; ni < 4; ni++)
            #pragma unroll
            for (int e = 0; e < 4; e++) acc[mi][ni][e] = 0.f;

    float4 va[2], vb[2];

    auto load_tiles = [&](int k0) {
        #pragma unroll
        for (int i = 0; i < 2; i++) {
            int f = tid * 2 + i;
            if (TA == 0) {
                int row = f >> 2, c4 = (f & 3) * 4;
                va[i] = *(const float4*)&A[(size_t)(bm + row) * lda + k0 + c4];
            } else {
                int kr = f >> 5, m0 = (f & 31) * 4;
                va[i] = *(const float4*)&A[(size_t)(k0 + kr) * lda + bm + m0];
            }
            if (TB == 1) {
                int row = f >> 2, c4 = (f & 3) * 4;
                vb[i] = *(const float4*)&B[(size_t)(bn + row) * ldb + k0 + c4];
            } else {
                int kr = f >> 5, n0 = (f & 31) * 4;
                vb[i] = *(const float4*)&B[(size_t)(k0 + kr) * ldb + bn + n0];
            }
        }
    };
    auto stage_tiles = [&]() {
        #pragma unroll
        for (int i = 0; i < 2; i++) {
            int f = tid * 2 + i;
            float4 v = va[i];
            if (TA == 0) {
                int row = f >> 2, c4 = (f & 3) * 4;
                __nv_bfloat16 h0, h1, h2, h3, l0, l1, l2, l3;
                bsplit(v.x, h0, l0); bsplit(v.y, h1, l1);
                bsplit(v.z, h2, l2); bsplit(v.w, h3, l3);
                *(uint2*)&Ash[row][c4] = make_uint2(bpack(h0, h1), bpack(h2, h3));
                *(uint2*)&Asl[row][c4] = make_uint2(bpack(l0, l1), bpack(l2, l3));
            } else {
                int kr = f >> 5, m0 = (f & 31) * 4;
                __nv_bfloat16 h, l;
                bsplit(v.x, h, l); Ash[m0 + 0][kr] = h; Asl[m0 + 0][kr] = l;
                bsplit(v.y, h, l); Ash[m0 + 1][kr] = h; Asl[m0 + 1][kr] = l;
                bsplit(v.z, h, l); Ash[m0 + 2][kr] = h; Asl[m0 + 2][kr] = l;
                bsplit(v.w, h, l); Ash[m0 + 3][kr] = h; Asl[m0 + 3][kr] = l;
            }
            v = vb[i];
            if (TB == 1) {
                int row = f >> 2, c4 = (f & 3) * 4;
                __nv_bfloat16 h0, h1, h2, h3, l0, l1, l2, l3;
                bsplit(v.x, h0, l0); bsplit(v.y, h1, l1);
                bsplit(v.z, h2, l2); bsplit(v.w, h3, l3);
                *(uint2*)&Bsh[row][c4] = make_uint2(bpack(h0, h1), bpack(h2, h3));
                *(uint2*)&Bsl[row][c4] = make_uint2(bpack(l0, l1), bpack(l2, l3));
            } else {
                int kr = f >> 5, n0 = (f & 31) * 4;
                __nv_bfloat16 h, l;
                bsplit(v.x, h, l); Bsh[n0 + 0][kr] = h; Bsl[n0 + 0][kr] = l;
                bsplit(v.y, h, l); Bsh[n0 + 1][kr] = h; Bsl[n0 + 1][kr] = l;
                bsplit(v.z, h, l); Bsh[n0 + 2][kr] = h; Bsl[n0 + 2][kr] = l;
                bsplit(v.w, h, l); Bsh[n0 + 3][kr] = h; Bsl[n0 + 3][kr] = l;
            }
        }
    };

    load_tiles(0);
    for (int k0 = 0; k0 < K; k0 += 16) {
        __syncthreads();
        stage_tiles();
        __syncthreads();
        if (k0 + 16 < K) load_tiles(k0 + 16);

        const int fr = lane >> 2;
        const int fc = (lane & 3) * 2;
        uint32_t bh[4][2], bl[4][2];
        #pragma unroll
        for (int ni = 0; ni < 4; ni++) {
            int nr = wn + ni * 8 + fr;
            bh[ni][0] = *(const uint32_t*)&Bsh[nr][fc];
            bh[ni][1] = *(const uint32_t*)&Bsh[nr][fc + 8];
            bl[ni][0] = *(const uint32_t*)&Bsl[nr][fc];
            bl[ni][1] = *(const uint32_t*)&Bsl[nr][fc + 8];
        }
        #pragma unroll
        for (int mi = 0; mi < 4; mi++) {
            int r0 = wm + mi * 16 + fr;
            uint32_t ah[4], al[4];
            ah[0] = *(const uint32_t*)&Ash[r0][fc];
            ah[1] = *(const uint32_t*)&Ash[r0 + 8][fc];
            ah[2] = *(const uint32_t*)&Ash[r0][fc + 8];
            ah[3] = *(const uint32_t*)&Ash[r0 + 8][fc + 8];
            al[0] = *(const uint32_t*)&Asl[r0][fc];
            al[1] = *(const uint32_t*)&Asl[r0 + 8][fc];
            al[2] = *(const uint32_t*)&Asl[r0][fc + 8];
            al[3] = *(const uint32_t*)&Asl[r0 + 8][fc + 8];
            #pragma unroll
            for (int ni = 0; ni < 4; ni++) {
                mma16816(acc[mi][ni], ah, bh[ni]);
                mma16816(acc[mi][ni], ah, bl[ni]);
                mma16816(acc[mi][ni], al, bh[ni]);
            }
        }
    }

    const int fr = lane >> 2;
    const int fc = (lane & 3) * 2;
    #pragma unroll
    for (int mi = 0; mi < 4; mi++) {
        int r = bm + wm + mi * 16 + fr;
        #pragma unroll
        for (int ni = 0; ni < 4; ni++) {
            int c = bn + wn + ni * 8 + fc;
            float v0 = alpha * acc[mi][ni][0];
            float v1 = alpha * acc[mi][ni][1];
            float v2 = alpha * acc[mi][ni][2];
            float v3 = alpha * acc[mi][ni][3];
            *(float2*)&C[(size_t)r * ldc + c] = make_float2(v0, v1);
            *(float2*)&C[(size_t)(r + 8) * ldc + c] = make_float2(v2, v3);
            if (Kout) {
                *(float2*)&Kout[(size_t)r * ldc + c] =
                    make_float2(__expf(v0 - LSE_C), __expf(v1 - LSE_C));
                *(float2*)&Kout[(size_t)(r + 8) * ldc + c] =
                    make_float2(__expf(v2 - LSE_C), __expf(v3 - LSE_C));
            }
        }
    }
}

// ---------------------------------------------------------------------------
// Elementwise / reduction kernels
// ---------------------------------------------------------------------------
__global__ void zero_acc_kernel(double* a) { if (threadIdx.x < 16) a[threadIdx.x] = 0.0; }
__global__ void set_vec_kernel(float* p, int n, float val) {
    int i = blockIdx.x * blockDim.x + threadIdx.x;
    if (i < n) p[i] = val;
}

__global__ void rownorm_kernel(const float* __restrict__ in, float* __restrict__ out, int D) {
    int row = blockIdx.x;
    const float* r = in + (size_t)row * D;
    float ss = 0.f;
    for (int i = threadIdx.x * 4; i < D; i += blockDim.x * 4) {
        float4 v = *(const float4*)&r[i];
        ss += v.x * v.x + v.y * v.y + v.z * v.z + v.w * v.w;
    }
    ss = blockSum(ss);
    __shared__ float s_inv;
    if (threadIdx.x == 0) s_inv = 1.f / fmaxf(sqrtf(ss), 1e-8f);
    __syncthreads();
    float inv = s_inv;
    for (int i = threadIdx.x * 4; i < D; i += blockDim.x * 4) {
        float4 v = *(const float4*)&r[i];
        v.x *= inv; v.y *= inv; v.z *= inv; v.w *= inv;
        *(float4*)&out[(size_t)row * D + i] = v;
    }
}

__global__ void quadnorm_kernel(const float* __restrict__ X, const float* __restrict__ W,
                                float* __restrict__ out, int D) {
    int row = blockIdx.x;
    const float* xr = X + (size_t)row * D;
    const float* wr = W + (size_t)row * D;
    float ss = 0.f;
    for (int i = threadIdx.x * 4; i < D; i += blockDim.x * 4) {
        float4 a = *(const float4*)&xr[i];
        float4 b = *(const float4*)&wr[i];
        ss += a.x * b.x + a.y * b.y + a.z * b.z + a.w * b.w;
    }
    ss = blockSum(ss);
    __shared__ float s_inv;
    if (threadIdx.x == 0) s_inv = 1.f / fmaxf(sqrtf(ss), 1e-8f);
    __syncthreads();
    float inv = s_inv;
    for (int i = threadIdx.x * 4; i < D; i += blockDim.x * 4) {
        float4 v = *(const float4*)&xr[i];
        v.x *= inv; v.y *= inv; v.z *= inv; v.w *= inv;
        *(float4*)&out[(size_t)row * D + i] = v;
    }
}

__global__ void scale_rows_sqrt_kernel(const float* __restrict__ X, const float* __restrict__ a,
                                       float* __restrict__ out, int D) {
    int row = blockIdx.x;
    float sc = sqrtf(fmaxf(a[row], 0.f));
    for (int i = threadIdx.x * 4; i < D; i += blockDim.x * 4) {
        float4 v = *(const float4*)&X[(size_t)row * D + i];
        v.x *= sc; v.y *= sc; v.z *= sc; v.w *= sc;
        *(float4*)&out[(size_t)row * D + i] = v;
    }
}

__global__ void scale_rows_kernel(const float* __restrict__ X, const float* __restrict__ a,
                                  float* __restrict__ out, int D) {
    int row = blockIdx.x;
    float sc = a[row];
    for (int i = threadIdx.x * 4; i < D; i += blockDim.x * 4) {
        float4 v = *(const float4*)&X[(size_t)row * D + i];
        v.x *= sc; v.y *= sc; v.z *= sc; v.w *= sc;
        *(float4*)&out[(size_t)row * D + i] = v;
    }
}

// ---- scaling-domain Sinkhorn passes (exp-free) ----
// u[i] = inv_n / sum_j K[i,j]*w[j]
__global__ void sink_row_kernel(const float* __restrict__ K, const float* __restrict__ w,
                                float* __restrict__ u, int ny, float inv_n) {
    int row = blockIdx.x;
    const float* Kr = K + (size_t)row * ny;
    float s = 0.f;
    for (int c = threadIdx.x * 4; c < ny; c += blockDim.x * 4) {
        float4 k = *(const float4*)&Kr[c];
        float4 ww = *(const float4*)&w[c];
        s += k.x * ww.x + k.y * ww.y + k.z * ww.z + k.w * ww.w;
    }
    s = blockSum(s);
    if (threadIdx.x == 0) u[row] = inv_n / s;
}

// arow[i] = u[i] * sum_j K[i,j]*w[j]  (final plan row marginal)
__global__ void sink_row_marg_kernel(const float* __restrict__ K, const float* __restrict__ w,
                                     const float* __restrict__ u, float* __restrict__ arow, int ny) {
    int row = blockIdx.x;
    const float* Kr = K + (size_t)row * ny;
    float s = 0.f;
    for (int c = threadIdx.x * 4; c < ny; c += blockDim.x * 4) {
        float4 k = *(const float4*)&Kr[c];
        float4 ww = *(const float4*)&w[c];
        s += k.x * ww.x + k.y * ww.y + k.z * ww.z + k.w * ww.w;
    }
    s = blockSum(s);
    if (threadIdx.x == 0) arow[row] = u[row] * s;
}

// ps[chunk, col] = partial sum_i K[i,col]*u[i]
__global__ void sink_col_partial_kernel(const float* __restrict__ K, const float* __restrict__ u,
                                        float* __restrict__ ps, int nx, int ny, int chunk) {
    int col = blockIdx.x * blockDim.x + threadIdx.x;
    int r0 = blockIdx.y * chunk;
    int r1 = min(r0 + chunk, nx);
    float s = 0.f;
    for (int r = r0; r < r1; r += 4) {
        s += K[(size_t)r * ny + col] * __ldg(&u[r])
           + K[(size_t)(r + 1) * ny + col] * __ldg(&u[r + 1])
           + K[(size_t)(r + 2) * ny + col] * __ldg(&u[r + 2])
           + K[(size_t)(r + 3) * ny + col] * __ldg(&u[r + 3]);
    }
    ps[(size_t)blockIdx.y * ny + col] = s;
}

// w[j] = inv_n / sum_chunks ps
__global__ void sink_col_combine_kernel(const float* __restrict__ ps, float* __restrict__ w,
                                        int ny, int nch, float inv_n) {
    int col = blockIdx.x * blockDim.x + threadIdx.x;
    float s = 0.f;
    for (int c = 0; c < nch; c++) s += ps[(size_t)c * ny + col];
    w[col] = inv_n / s;
}

// bcol[j] = w[j] * sum_chunks ps  (final plan col marginal)
__global__ void sink_col_marg_combine_kernel(const float* __restrict__ ps, const float* __restrict__ w,
                                             float* __restrict__ bcol, int ny, int nch) {
    int col = blockIdx.x * blockDim.x + threadIdx.x;
    float s = 0.f;
    for (int c = 0; c < nch; c++) s += ps[(size_t)c * ny + col];
    bcol[col] = w[col] * s;
}

__global__ void logdiff_kernel(const float* __restrict__ a, const float* __restrict__ b,
                               float* __restrict__ out, int n) {
    int i = blockIdx.x * blockDim.x + threadIdx.x;
    if (i < n) out[i] = __logf(a[i]) - __logf(b[i]);
}

__global__ void marg_acc_kernel(const float* __restrict__ sums, int n, double* acc) {
    int i = blockIdx.x * blockDim.x + threadIdx.x;
    double t = 0.0;
    if (i < n) {
        float d = sums[i] - 1.f / (float)n;
        t = (double)d * (double)d;
    }
    t = blockSumD(t);
    if (threadIdx.x == 0) atomicAdd(&acc[S_MARG], t);
}

// SAIL: sum softplus(-z), z = Mp*0.5*target ; n power of two, shift = log2(n)
__global__ void sail_acc_kernel(const float* __restrict__ Mp, int n, int shift, double* acc) {
    size_t total4 = ((size_t)n * n) >> 2;
    double t = 0.0;
    for (size_t i4 = (size_t)blockIdx.x * blockDim.x + threadIdx.x; i4 < total4;
         i4 += (size_t)gridDim.x * blockDim.x) {
        size_t base = i4 * 4;
        int i = (int)(base >> shift);
        int j = (int)(base & (size_t)(n - 1));
        float4 m = *(const float4*)&Mp[base];
        float mv[4] = {m.x, m.y, m.z, m.w};
        float acc4 = 0.f;
        #pragma unroll
        for (int k = 0; k < 4; k++) {
            float z = mv[k] * 0.5f;
            if (j + k != i) z = -z;
            float a = -z;
            acc4 += fmaxf(a, 0.f) + log1pf(__expf(-fabsf(a)));
        }
        t += (double)acc4;
    }
    t = blockSumD(t);
    if (threadIdx.x == 0) atomicAdd(&acc[S_SAIL], t);
}

// diag (scaling form): logp_ii = Mp_ii - C + log u_i + log v_i
__global__ void diag_acc_kernel(const float* __restrict__ Mp, const float* __restrict__ u,
                                const float* __restrict__ v, int n, float logN, double* acc) {
    int i = blockIdx.x * blockDim.x + threadIdx.x;
    double ti = 0.0, te = 0.0;
    if (i < n) {
        float mii = Mp[(size_t)i * n + i];
        ti = (double)(mii - LSE_C + __logf(u[i]) + __logf(v[i]) + logN);
        te = (double)((1.f - mii * 0.05f) * 0.5f);
    }
    ti = blockSumD(ti);
    __shared__ double sh;
    if (threadIdx.x == 0) sh = ti;
    te = blockSumD(te);
    if (threadIdx.x == 0) {
        atomicAdd(&acc[S_IMP], sh);
        atomicAdd(&acc[S_EXP], te);
    }
}

// L_ot = sum pa * (la - lu), exp-free:
// pa = Ka*ua*va ; la - lu = (Ca - Mu) + d[i] + e[j]
__global__ void ot_acc_kernel(const float* __restrict__ Ka, const float* __restrict__ Ca,
                              const float* __restrict__ Mu,
                              const float* __restrict__ ua, const float* __restrict__ va,
                              const float* __restrict__ d, const float* __restrict__ e,
                              int n, int shift, double* acc) {
    size_t total4 = ((size_t)n * n) >> 2;
    double t = 0.0;
    for (size_t i4 = (size_t)blockIdx.x * blockDim.x + threadIdx.x; i4 < total4;
         i4 += (size_t)gridDim.x * blockDim.x) {
        size_t base = i4 * 4;
        int i = (int)(base >> shift);
        int j = (int)(base & (size_t)(n - 1));
        float4 k4 = *(const float4*)&Ka[base];
        float4 c4 = *(const float4*)&Ca[base];
        float4 m4 = *(const float4*)&Mu[base];
        float4 vj = *(const float4*)&va[j];
        float4 ej = *(const float4*)&e[j];
        float uai = __ldg(&ua[i]);
        float di = __ldg(&d[i]);
        float s = 0.f;
        s += k4.x * uai * vj.x * ((c4.x - m4.x) + di + ej.x);
        s += k4.y * uai * vj.y * ((c4.y - m4.y) + di + ej.y);
        s += k4.z * uai * vj.z * ((c4.z - m4.z) + di + ej.z);
        s += k4.w * uai * vj.w * ((c4.w - m4.w) + di + ej.w);
        t += (double)s;
    }
    t = blockSumD(t);
    if (threadIdx.x == 0) atomicAdd(&acc[S_OT], t);
}

__global__ void dot_acc_kernel(const float* __restrict__ A, const float* __restrict__ B,
                               int n, double* acc, int slot) {
    double t = 0.0;
    for (int i = blockIdx.x * blockDim.x + threadIdx.x; i < n; i += gridDim.x * blockDim.x)
        t += (double)A[i] * (double)B[i];
    t = blockSumD(t);
    if (threadIdx.x == 0) atomicAdd(&acc[slot], t);
}

__global__ void sumsq_acc_kernel(const float* __restrict__ A, int n, double* acc, int slot) {
    double t = 0.0;
    for (int i = blockIdx.x * blockDim.x + threadIdx.x; i < n; i += gridDim.x * blockDim.x)
        t += (double)A[i] * (double)A[i];
    t = blockSumD(t);
    if (threadIdx.x == 0) atomicAdd(&acc[slot], t);
}

__global__ void finalize_kernel(const double* __restrict__ acc, float* __restrict__ out) {
    double L = acc[S_MARG]
             + acc[S_SAIL] / ((double)NP * (double)NP)
             + acc[S_EXP] / (double)NP
             - acc[S_IMP] / (double)NP
             + acc[S_OT]
             + (acc[S_N1] + acc[S_N2] - 2.0 * acc[S_DT]) / ((double)NX * (double)NX)
             + (acc[S_SQA] + acc[S_SQB] - 2.0 * acc[S_SQG]);
    out[0] = (float)L;
}

// ---------------------------------------------------------------------------
// Host side
// ---------------------------------------------------------------------------
static inline void launch_gemm(int TA, int TB, const float* A, const float* B, float* C,
                               int M, int N, int K, int lda, int ldb, int ldc, float alpha,
                               float* Kout = nullptr) {
    dim3 grid(N / 128, M / 128), block(256);
    if (TA == 0 && TB == 0) gemm_mma_kernel<0, 0><<<grid, block>>>(A, B, C, Kout, K, lda, ldb, ldc, alpha);
    else if (TA == 0 && TB == 1) gemm_mma_kernel<0, 1><<<grid, block>>>(A, B, C, Kout, K, lda, ldb, ldc, alpha);
    else gemm_mma_kernel<1, 0><<<grid, block>>>(A, B, C, Kout, K, lda, ldb, ldc, alpha);
}

// scaling-domain Sinkhorn: u = a/(K w), w = b/(K^T u), 10 iters, init w=1
static void run_sinkhorn_scaling(const float* K, float* u, float* w, int nx, int ny, float* ps) {
    float inv_a = 1.f / (float)nx, inv_b = 1.f / (float)ny;
    const int CH = 256;
    int nch = nx / CH;
    set_vec_kernel<<<(ny + 255) / 256, 256>>>(w, ny, 1.f);
    dim3 cgrid(ny / 256, nch);
    for (int it = 0; it < SINK_IT; it++) {
        sink_row_kernel<<<nx, 256>>>(K, w, u, ny, inv_a);
        sink_col_partial_kernel<<<cgrid, 256>>>(K, u, ps, nx, ny, CH);
        sink_col_combine_kernel<<<ny / 256, 256>>>(ps, w, ny, nch, inv_b);
    }
}

#define GETSYM(ptr, sym) do { void* _t; cudaGetSymbolAddress(&_t, sym); ptr = (float*)_t; } while (0)

extern "C" void kernel_launch(void* const* d_in, const int* in_sizes, int n_in,
                              void* d_out, int out_size) {
    const float* fXp = (const float*)d_in[0];   // 2048x256
    const float* fYp = (const float*)d_in[1];   // 2048x256
    const float* X   = (const float*)d_in[2];   // 4096x768
    const float* Y   = (const float*)d_in[3];   // 4096x512
    const float* fX  = (const float*)d_in[4];   // 4096x256
    const float* fY  = (const float*)d_in[5];   // 4096x256
    const float* Xan = (const float*)d_in[6];   // 4096x768
    const float* Yan = (const float*)d_in[7];   // 4096x512
    float* out = (float*)d_out;

    float *Mp, *Kp, *Mu, *Ku, *Ca, *Ka, *Xa, *Ya, *Xu, *Yu, *Xn, *Yn, *fXn, *fYn, *fXpn, *fYpn;
    float *W, *T, *Sxx, *Syy, *Sxy, *Gxx, *Gyy, *Gfx, *Gfy, *Gxf, *Gfyy, *U1, *V1, *W1;
    float *Ag, *Bg, *Gg, *up, *wp, *uu, *wu, *ua, *wa, *arow, *bcol, *ap, *bp, *dv, *ev, *ps;
    double* acc;
    GETSYM(Mp, g_Mp); GETSYM(Kp, g_Kp); GETSYM(Mu, g_Mu); GETSYM(Ku, g_Ku);
    GETSYM(Ca, g_Ca); GETSYM(Ka, g_Ka);
    GETSYM(Xa, g_Xa); GETSYM(Ya, g_Ya); GETSYM(Xu, g_Xu); GETSYM(Yu, g_Yu);
    GETSYM(Xn, g_Xn); GETSYM(Yn, g_Yn); GETSYM(fXn, g_fXn); GETSYM(fYn, g_fYn);
    GETSYM(fXpn, g_fXpn); GETSYM(fYpn, g_fYpn);
    GETSYM(W, g_W); GETSYM(T, g_T);
    GETSYM(Sxx, g_Sxx); GETSYM(Syy, g_Syy); GETSYM(Sxy, g_Sxy);
    GETSYM(Gxx, g_Gxx); GETSYM(Gyy, g_Gyy); GETSYM(Gfx, g_Gfx); GETSYM(Gfy, g_Gfy);
    GETSYM(Gxf, g_Gxf); GETSYM(Gfyy, g_Gfyy); GETSYM(U1, g_U1); GETSYM(V1, g_V1); GETSYM(W1, g_W1);
    GETSYM(Ag, g_Ag); GETSYM(Bg, g_Bg); GETSYM(Gg, g_Gg);
    GETSYM(up, g_up); GETSYM(wp, g_wp); GETSYM(uu, g_uu); GETSYM(wu, g_wu);
    GETSYM(ua, g_ua); GETSYM(wa, g_wa);
    GETSYM(arow, g_arow); GETSYM(bcol, g_bcol); GETSYM(ap, g_ap); GETSYM(bp, g_bp);
    GETSYM(dv, g_dvec); GETSYM(ev, g_evec);
    GETSYM(ps, g_ps);
    { void* _t; cudaGetSymbolAddress(&_t, g_acc); acc = (double*)_t; }

    zero_acc_kernel<<<1, 32>>>(acc);               // 1
    rownorm_kernel<<<NX, 256>>>(fX, fXn, DF);      // 2
    rownorm_kernel<<<NX, 256>>>(fY, fYn, DF);      // 3
    rownorm_kernel<<<NX, 256>>>(Xan, Xa, DX);      // 4
    rownorm_kernel<<<NX, 256>>>(Yan, Ya, DY);      // 5
    launch_gemm(0, 1, fXn, fYn, Mu, NX, NX, DF, DF, DF, NX, EPS_INV, Ku);  // 6 <- profiled

    rownorm_kernel<<<NP, 256>>>(fXp, fXpn, DF);
    rownorm_kernel<<<NP, 256>>>(fYp, fYpn, DF);
    rownorm_kernel<<<NX, 256>>>(X, Xu, DX);
    rownorm_kernel<<<NX, 256>>>(Y, Yu, DY);

    // --- anchor covariances ---
    launch_gemm(1, 0, Xa, Xa, Sxx, DX, DX, NX, DX, DX, DX, 1.f / NX);
    launch_gemm(1, 0, Ya, Ya, Syy, DY, DY, NX, DY, DY, DY, 1.f / NX);
    launch_gemm(1, 0, Xa, Ya, Sxy, DX, DY, NX, DX, DY, DY, 1.f / NX);

    // --- pairs cosine matrix (log + exp kernels) ---
    launch_gemm(0, 1, fXpn, fYpn, Mp, NP, NP, DF, DF, DF, NP, EPS_INV, Kp);

    // --- scaling-domain sinkhorns (exp-free loops) ---
    run_sinkhorn_scaling(Kp, up, wp, NP, NP, ps);
    run_sinkhorn_scaling(Ku, uu, wu, NX, NX, ps);

    // --- pairs plan stats ---
    sink_row_marg_kernel<<<NP, 256>>>(Kp, wp, up, ap, NP);
    sink_col_partial_kernel<<<dim3(NP / 256, NP / 256), 256>>>(Kp, up, ps, NP, NP, 256);
    sink_col_marg_combine_kernel<<<NP / 256, 256>>>(ps, wp, bp, NP, NP / 256);
    marg_acc_kernel<<<NP / 256, 256>>>(ap, NP, acc);
    marg_acc_kernel<<<NP / 256, 256>>>(bp, NP, acc);
    sail_acc_kernel<<<1024, 256>>>(Mp, NP, 11, acc);
    diag_acc_kernel<<<NP / 256, 256>>>(Mp, up, wp, NP, logf((float)NP), acc);

    // --- latent plan marginals ---
    sink_row_marg_kernel<<<NX, 256>>>(Ku, wu, uu, arow, NX);
    sink_col_partial_kernel<<<dim3(NX / 256, NX / 256), 256>>>(Ku, uu, ps, NX, NX, 256);
    sink_col_marg_combine_kernel<<<NX / 256, 256>>>(ps, wu, bcol, NX, NX / 256);
    marg_acc_kernel<<<NX / 256, 256>>>(arow, NX, acc);
    marg_acc_kernel<<<NX / 256, 256>>>(bcol, NX, acc);

    // --- anchor-space normalization + plan ---
    launch_gemm(0, 0, X, Sxx, W, NX, DX, DX, DX, DX, DX, 1.f);
    quadnorm_kernel<<<NX, 256>>>(X, W, Xn, DX);
    launch_gemm(0, 0, Y, Syy, W, NX, DY, DY, DY, DY, DY, 1.f);
    quadnorm_kernel<<<NX, 256>>>(Y, W, Yn, DY);
    launch_gemm(0, 0, Xn, Sxy, T, NX, DY, DX, DX, DY, DY, 1.f);
    launch_gemm(0, 1, T, Yn, Ca, NX, NX, DY, DY, DY, NX, EPS_INV, Ka);
    run_sinkhorn_scaling(Ka, ua, wa, NX, NX, ps);

    // --- L_ot (exp-free) ---
    logdiff_kernel<<<NX / 256, 256>>>(ua, uu, dv, NX);
    logdiff_kernel<<<NX / 256, 256>>>(wa, wu, ev, NX);
    ot_acc_kernel<<<2048, 256>>>(Ka, Ca, Mu, ua, wa, dv, ev, NX, 12, acc);

    // --- L_div ---
    launch_gemm(1, 0, Xn, Xn, Gxx, DX, DX, NX, DX, DX, DX, 1.f);
    launch_gemm(1, 0, Yn, Yn, Gyy, DY, DY, NX, DY, DY, DY, 1.f);
    launch_gemm(1, 0, fXn, fXn, Gfx, DF, DF, NX, DF, DF, DF, 1.f);
    launch_gemm(1, 0, fYn, fYn, Gfy, DF, DF, NX, DF, DF, DF, 1.f);
    launch_gemm(1, 0, Xn, fXn, Gxf, DX, DF, NX, DX, DF, DF, 1.f);
    launch_gemm(1, 0, fYn, Yn, Gfyy, DF, DY, NX, DF, DY, DY, 1.f);
    launch_gemm(0, 0, Gxx, Sxy, U1, DX, DY, DX, DX, DY, DY, 1.f);
    launch_gemm(0, 0, U1, Gyy, V1, DX, DY, DY, DY, DY, DY, 1.f);
    launch_gemm(0, 0, Gxf, Gfyy, W1, DX, DY, DF, DF, DY, DY, 1.f);
    dot_acc_kernel<<<256, 256>>>(V1, Sxy, DX * DY, acc, S_N1);
    dot_acc_kernel<<<256, 256>>>(Gfx, Gfy, DF * DF, acc, S_N2);
    dot_acc_kernel<<<256, 256>>>(W1, Sxy, DX * DY, acc, S_DT);

    // --- L_gw ---
    scale_rows_sqrt_kernel<<<NX, 256>>>(Xu, arow, W, DX);
    launch_gemm(1, 0, W, W, Ag, DX, DX, NX, DX, DX, DX, 1.f);
    sumsq_acc_kernel<<<256, 256>>>(Ag, DX * DX, acc, S_SQA);
    scale_rows_sqrt_kernel<<<NX, 256>>>(Yu, bcol, W, DY);
    launch_gemm(1, 0, W, W, Bg, DY, DY, NX, DY, DY, DY, 1.f);
    sumsq_acc_kernel<<<256, 256>>>(Bg, DY * DY, acc, S_SQB);
    // ||Xu^T P Yu||^2 with P = diag(u) Ku diag(w):
    scale_rows_kernel<<<NX, 256>>>(Yu, wu, W, DY);           // W = diag(w) Yu
    launch_gemm(0, 0, Ku, W, T, NX, DY, NX, NX, DY, DY, 1.f); // T = Ku (w∘Yu)
    scale_rows_kernel<<<NX, 256>>>(Xu, uu, Xa, DX);          // Xa = diag(u) Xu (reuse)
    launch_gemm(1, 0, Xa, T, Gg, DX, DY, NX, DX, DY, DY, 1.f);
    sumsq_acc_kernel<<<256, 256>>>(Gg, DX * DY, acc, S_SQG);

    finalize_kernel<<<1, 1>>>(acc, out);
}

// round 11
// speedup vs baseline: 3.8404x; 3.2449x over previous
#include <cuda_runtime.h>
#include <cuda_bf16.h>
#include <math.h>
#include <stdint.h>

#define NP 2048
#define NX 4096
#define DX 768
#define DY 512
#define DF 256
#define EPS_INV 20.0f
#define SINK_IT 10
#define LSE_C 20.0f

#define S_MARG 0
#define S_SAIL 1
#define S_EXP  2
#define S_IMP  3
#define S_OT   4
#define S_N1   5
#define S_N2   6
#define S_DT   7
#define S_SQA  8
#define S_SQB  9
#define S_SQG  10

// ---------------------------------------------------------------------------
// Static device scratch
// ---------------------------------------------------------------------------
__device__ __align__(128) float g_Mp[(size_t)NP * NP];
__device__ __align__(128) float g_Kp[(size_t)NP * NP];
__device__ __align__(128) float g_Mu[(size_t)NX * NX];
__device__ __align__(128) float g_Ku[(size_t)NX * NX];
__device__ __align__(128) float g_Ca[(size_t)NX * NX];   // anchor log kernel + split-K partial scratch
__device__ __align__(128) float g_Ka[(size_t)NX * NX];
__device__ __align__(128) float g_Xa[NX * DX];
__device__ __align__(128) float g_Ya[NX * DY];
__device__ __align__(128) float g_Xu[NX * DX];
__device__ __align__(128) float g_Yu[NX * DY];
__device__ __align__(128) float g_Xn[NX * DX];
__device__ __align__(128) float g_Yn[NX * DY];
__device__ __align__(128) float g_fXn[NX * DF];
__device__ __align__(128) float g_fYn[NX * DF];
__device__ __align__(128) float g_fXpn[NP * DF];
__device__ __align__(128) float g_fYpn[NP * DF];
__device__ __align__(128) float g_W[NX * DX];
__device__ __align__(128) float g_T[NX * DY];
__device__ __align__(128) float g_Sxx[DX * DX];
__device__ __align__(128) float g_Syy[DY * DY];
__device__ __align__(128) float g_Sxy[DX * DY];
__device__ __align__(128) float g_Gxx[DX * DX];
__device__ __align__(128) float g_Gyy[DY * DY];
__device__ __align__(128) float g_Gfx[DF * DF];
__device__ __align__(128) float g_Gfy[DF * DF];
__device__ __align__(128) float g_Gxf[DX * DF];
__device__ __align__(128) float g_Gfyy[DF * DY];
__device__ __align__(128) float g_U1[DX * DY];
__device__ __align__(128) float g_V1[DX * DY];
__device__ __align__(128) float g_W1[DX * DY];
__device__ __align__(128) float g_Ag[DX * DX];
__device__ __align__(128) float g_Bg[DY * DY];
__device__ __align__(128) float g_Gg[DX * DY];
__device__ __align__(16) float g_up[NP], g_wp[NP];
__device__ __align__(16) float g_uu[NX], g_wu[NX];
__device__ __align__(16) float g_ua[NX], g_wa[NX];
__device__ __align__(16) float g_arow[NX], g_bcol[NX];
__device__ __align__(16) float g_ap[NP];
__device__ __align__(16) float g_dvec[NX], g_evec[NX];
__device__ __align__(128) float g_ps[16 * NX];
__device__ double g_acc[16];

// ---------------------------------------------------------------------------
// Reduction helpers
// ---------------------------------------------------------------------------
__device__ __forceinline__ float warpSum(float v) {
    #pragma unroll
    for (int o = 16; o; o >>= 1) v += __shfl_xor_sync(0xffffffffu, v, o);
    return v;
}
__device__ __forceinline__ double warpSumD(double v) {
    #pragma unroll
    for (int o = 16; o; o >>= 1) v += __shfl_xor_sync(0xffffffffu, v, o);
    return v;
}
__device__ double blockSumD(double v) {
    __shared__ double s[32];
    __syncthreads();
    int lane = threadIdx.x & 31, wid = threadIdx.x >> 5;
    v = warpSumD(v);
    if (lane == 0) s[wid] = v;
    __syncthreads();
    if (wid == 0) {
        int nw = blockDim.x >> 5;
        v = (lane < nw) ? s[lane] : 0.0;
        v = warpSumD(v);
    }
    return v;
}

// ---------------------------------------------------------------------------
// Tensor-core GEMM, split-bf16 (bf16x3), reg prefetch, optional split-K.
// grid.z = S splits; Kc = K/S; for S>1 caller passes C=partial, alpha=1,
// mnsize=M*N and reduces afterwards.
// ---------------------------------------------------------------------------
#define ASTRIDE 24

__device__ __forceinline__ void bsplit(float x, __nv_bfloat16& h, __nv_bfloat16& l) {
    h = __float2bfloat16(x);
    l = __float2bfloat16(x - __bfloat162float(h));
}
__device__ __forceinline__ uint32_t bpack(__nv_bfloat16 a, __nv_bfloat16 b) {
    __nv_bfloat162 t; t.x = a; t.y = b;
    return *reinterpret_cast<uint32_t*>(&t);
}
__device__ __forceinline__ void mma16816(float* c, const uint32_t* a, const uint32_t* b) {
    asm volatile(
        "mma.sync.aligned.m16n8k16.row.col.f32.bf16.bf16.f32 "
        "{%0,%1,%2,%3}, {%4,%5,%6,%7}, {%8,%9}, {%0,%1,%2,%3};\n"
        : "+f"(c[0]), "+f"(c[1]), "+f"(c[2]), "+f"(c[3])
        : "r"(a[0]), "r"(a[1]), "r"(a[2]), "r"(a[3]), "r"(b[0]), "r"(b[1]));
}

template <int TA, int TB>
__global__ __launch_bounds__(256, 2)
void gemm_mma_kernel(const float* __restrict__ A, const float* __restrict__ B,
                     float* __restrict__ C, float* __restrict__ Kout,
                     int Kc, int lda, int ldb, int ldc, float alpha, size_t mnsize) {
    __shared__ __align__(16) __nv_bfloat16 Ash[128][ASTRIDE];
    __shared__ __align__(16) __nv_bfloat16 Asl[128][ASTRIDE];
    __shared__ __align__(16) __nv_bfloat16 Bsh[128][ASTRIDE];
    __shared__ __align__(16) __nv_bfloat16 Bsl[128][ASTRIDE];

    const int tid = threadIdx.x;
    const int warp = tid >> 5, lane = tid & 31;
    const int bm = blockIdx.y * 128, bn = blockIdx.x * 128;
    const int wm = (warp >> 2) * 64;
    const int wn = (warp & 3) * 32;
    const int kbeg = blockIdx.z * Kc;
    const int kend = kbeg + Kc;
    C += (size_t)blockIdx.z * mnsize;

    float acc[4][4][4];
    #pragma unroll
    for (int mi = 0; mi < 4; mi++)
        #pragma unroll
        for (int ni = 0; ni < 4; ni++)
            #pragma unroll
            for (int e = 0; e < 4; e++) acc[mi][ni][e] = 0.f;

    float4 va[2], vb[2];

    auto load_tiles = [&](int k0) {
        #pragma unroll
        for (int i = 0; i < 2; i++) {
            int f = tid * 2 + i;
            if (TA == 0) {
                int row = f >> 2, c4 = (f & 3) * 4;
                va[i] = *(const float4*)&A[(size_t)(bm + row) * lda + k0 + c4];
            } else {
                int kr = f >> 5, m0 = (f & 31) * 4;
                va[i] = *(const float4*)&A[(size_t)(k0 + kr) * lda + bm + m0];
            }
            if (TB == 1) {
                int row = f >> 2, c4 = (f & 3) * 4;
                vb[i] = *(const float4*)&B[(size_t)(bn + row) * ldb + k0 + c4];
            } else {
                int kr = f >> 5, n0 = (f & 31) * 4;
                vb[i] = *(const float4*)&B[(size_t)(k0 + kr) * ldb + bn + n0];
            }
        }
    };
    auto stage_tiles = [&]() {
        #pragma unroll
        for (int i = 0; i < 2; i++) {
            int f = tid * 2 + i;
            float4 v = va[i];
            if (TA == 0) {
                int row = f >> 2, c4 = (f & 3) * 4;
                __nv_bfloat16 h0, h1, h2, h3, l0, l1, l2, l3;
                bsplit(v.x, h0, l0); bsplit(v.y, h1, l1);
                bsplit(v.z, h2, l2); bsplit(v.w, h3, l3);
                *(uint2*)&Ash[row][c4] = make_uint2(bpack(h0, h1), bpack(h2, h3));
                *(uint2*)&Asl[row][c4] = make_uint2(bpack(l0, l1), bpack(l2, l3));
            } else {
                int kr = f >> 5, m0 = (f & 31) * 4;
                __nv_bfloat16 h, l;
                bsplit(v.x, h, l); Ash[m0 + 0][kr] = h; Asl[m0 + 0][kr] = l;
                bsplit(v.y, h, l); Ash[m0 + 1][kr] = h; Asl[m0 + 1][kr] = l;
                bsplit(v.z, h, l); Ash[m0 + 2][kr] = h; Asl[m0 + 2][kr] = l;
                bsplit(v.w, h, l); Ash[m0 + 3][kr] = h; Asl[m0 + 3][kr] = l;
            }
            v = vb[i];
            if (TB == 1) {
                int row = f >> 2, c4 = (f & 3) * 4;
                __nv_bfloat16 h0, h1, h2, h3, l0, l1, l2, l3;
                bsplit(v.x, h0, l0); bsplit(v.y, h1, l1);
                bsplit(v.z, h2, l2); bsplit(v.w, h3, l3);
                *(uint2*)&Bsh[row][c4] = make_uint2(bpack(h0, h1), bpack(h2, h3));
                *(uint2*)&Bsl[row][c4] = make_uint2(bpack(l0, l1), bpack(l2, l3));
            } else {
                int kr = f >> 5, n0 = (f & 31) * 4;
                __nv_bfloat16 h, l;
                bsplit(v.x, h, l); Bsh[n0 + 0][kr] = h; Bsl[n0 + 0][kr] = l;
                bsplit(v.y, h, l); Bsh[n0 + 1][kr] = h; Bsl[n0 + 1][kr] = l;
                bsplit(v.z, h, l); Bsh[n0 + 2][kr] = h; Bsl[n0 + 2][kr] = l;
                bsplit(v.w, h, l); Bsh[n0 + 3][kr] = h; Bsl[n0 + 3][kr] = l;
            }
        }
    };

    load_tiles(kbeg);
    for (int k0 = kbeg; k0 < kend; k0 += 16) {
        __syncthreads();
        stage_tiles();
        __syncthreads();
        if (k0 + 16 < kend) load_tiles(k0 + 16);

        const int fr = lane >> 2;
        const int fc = (lane & 3) * 2;
        uint32_t bh[4][2], bl[4][2];
        #pragma unroll
        for (int ni = 0; ni < 4; ni++) {
            int nr = wn + ni * 8 + fr;
            bh[ni][0] = *(const uint32_t*)&Bsh[nr][fc];
            bh[ni][1] = *(const uint32_t*)&Bsh[nr][fc + 8];
            bl[ni][0] = *(const uint32_t*)&Bsl[nr][fc];
            bl[ni][1] = *(const uint32_t*)&Bsl[nr][fc + 8];
        }
        #pragma unroll
        for (int mi = 0; mi < 4; mi++) {
            int r0 = wm + mi * 16 + fr;
            uint32_t ah[4], al[4];
            ah[0] = *(const uint32_t*)&Ash[r0][fc];
            ah[1] = *(const uint32_t*)&Ash[r0 + 8][fc];
            ah[2] = *(const uint32_t*)&Ash[r0][fc + 8];
            ah[3] = *(const uint32_t*)&Ash[r0 + 8][fc + 8];
            al[0] = *(const uint32_t*)&Asl[r0][fc];
            al[1] = *(const uint32_t*)&Asl[r0 + 8][fc];
            al[2] = *(const uint32_t*)&Asl[r0][fc + 8];
            al[3] = *(const uint32_t*)&Asl[r0 + 8][fc + 8];
            #pragma unroll
            for (int ni = 0; ni < 4; ni++) {
                mma16816(acc[mi][ni], ah, bh[ni]);
                mma16816(acc[mi][ni], ah, bl[ni]);
                mma16816(acc[mi][ni], al, bh[ni]);
            }
        }
    }

    const int fr = lane >> 2;
    const int fc = (lane & 3) * 2;
    #pragma unroll
    for (int mi = 0; mi < 4; mi++) {
        int r = bm + wm + mi * 16 + fr;
        #pragma unroll
        for (int ni = 0; ni < 4; ni++) {
            int c = bn + wn + ni * 8 + fc;
            float v0 = alpha * acc[mi][ni][0];
            float v1 = alpha * acc[mi][ni][1];
            float v2 = alpha * acc[mi][ni][2];
            float v3 = alpha * acc[mi][ni][3];
            *(float2*)&C[(size_t)r * ldc + c] = make_float2(v0, v1);
            *(float2*)&C[(size_t)(r + 8) * ldc + c] = make_float2(v2, v3);
            if (Kout) {
                *(float2*)&Kout[(size_t)r * ldc + c] =
                    make_float2(__expf(v0 - LSE_C), __expf(v1 - LSE_C));
                *(float2*)&Kout[(size_t)(r + 8) * ldc + c] =
                    make_float2(__expf(v2 - LSE_C), __expf(v3 - LSE_C));
            }
        }
    }
}

__global__ void splitk_reduce_kernel(const float* __restrict__ p, float* __restrict__ C,
                                     int mn, int S, float alpha) {
    int i = blockIdx.x * blockDim.x + threadIdx.x;
    if (i < mn) {
        float s = 0.f;
        for (int z = 0; z < S; z++) s += p[(size_t)z * mn + i];
        C[i] = alpha * s;
    }
}

// ---------------------------------------------------------------------------
// Elementwise / reduction kernels (warp-per-row where applicable)
// ---------------------------------------------------------------------------
__global__ void zero_acc_kernel(double* a) { if (threadIdx.x < 16) a[threadIdx.x] = 0.0; }
__global__ void set_vec_kernel(float* p, int n, float val) {
    int i = blockIdx.x * blockDim.x + threadIdx.x;
    if (i < n) p[i] = val;
}

// warp per row; D % 128 == 0; grid = rows/8, block = 256
__global__ void rownorm_kernel(const float* __restrict__ in, float* __restrict__ out, int D) {
    int row = blockIdx.x * 8 + (threadIdx.x >> 5);
    int lane = threadIdx.x & 31;
    const float* r = in + (size_t)row * D;
    float ss = 0.f;
    for (int i = lane * 4; i < D; i += 128) {
        float4 v = *(const float4*)&r[i];
        ss += v.x * v.x + v.y * v.y + v.z * v.z + v.w * v.w;
    }
    ss = warpSum(ss);
    float inv = 1.f / fmaxf(sqrtf(ss), 1e-8f);
    for (int i = lane * 4; i < D; i += 128) {
        float4 v = *(const float4*)&r[i];
        v.x *= inv; v.y *= inv; v.z *= inv; v.w *= inv;
        *(float4*)&out[(size_t)row * D + i] = v;
    }
}

__global__ void quadnorm_kernel(const float* __restrict__ X, const float* __restrict__ W,
                                float* __restrict__ out, int D) {
    int row = blockIdx.x * 8 + (threadIdx.x >> 5);
    int lane = threadIdx.x & 31;
    const float* xr = X + (size_t)row * D;
    const float* wr = W + (size_t)row * D;
    float ss = 0.f;
    for (int i = lane * 4; i < D; i += 128) {
        float4 a = *(const float4*)&xr[i];
        float4 b = *(const float4*)&wr[i];
        ss += a.x * b.x + a.y * b.y + a.z * b.z + a.w * b.w;
    }
    ss = warpSum(ss);
    float inv = 1.f / fmaxf(sqrtf(ss), 1e-8f);
    for (int i = lane * 4; i < D; i += 128) {
        float4 v = *(const float4*)&xr[i];
        v.x *= inv; v.y *= inv; v.z *= inv; v.w *= inv;
        *(float4*)&out[(size_t)row * D + i] = v;
    }
}

__global__ void scale_rows_sqrt_kernel(const float* __restrict__ X, const float* __restrict__ a,
                                       float* __restrict__ out, int D) {
    int row = blockIdx.x * 8 + (threadIdx.x >> 5);
    int lane = threadIdx.x & 31;
    float sc = sqrtf(fmaxf(a[row], 0.f));
    for (int i = lane * 4; i < D; i += 128) {
        float4 v = *(const float4*)&X[(size_t)row * D + i];
        v.x *= sc; v.y *= sc; v.z *= sc; v.w *= sc;
        *(float4*)&out[(size_t)row * D + i] = v;
    }
}

__global__ void scale_rows_kernel(const float* __restrict__ X, const float* __restrict__ a,
                                  float* __restrict__ out, int D) {
    int row = blockIdx.x * 8 + (threadIdx.x >> 5);
    int lane = threadIdx.x & 31;
    float sc = a[row];
    for (int i = lane * 4; i < D; i += 128) {
        float4 v = *(const float4*)&X[(size_t)row * D + i];
        v.x *= sc; v.y *= sc; v.z *= sc; v.w *= sc;
        *(float4*)&out[(size_t)row * D + i] = v;
    }
}

// ---- scaling-domain Sinkhorn passes ----
// warp per row: u[i] = inv_n / sum_j K[i,j]*w[j] ; grid = nx/8
__global__ void sink_row_kernel(const float* __restrict__ K, const float* __restrict__ w,
                                float* __restrict__ u, int ny, float inv_n) {
    int row = blockIdx.x * 8 + (threadIdx.x >> 5);
    int lane = threadIdx.x & 31;
    const float* Kr = K + (size_t)row * ny;
    float s = 0.f;
    for (int c = lane * 4; c < ny; c += 128) {
        float4 k = *(const float4*)&Kr[c];
        float4 ww = *(const float4*)&w[c];
        s += k.x * ww.x + k.y * ww.y + k.z * ww.z + k.w * ww.w;
    }
    s = warpSum(s);
    if (lane == 0) u[row] = inv_n / s;
}

// arow[i] = u[i] * sum_j K[i,j]*w[j]
__global__ void sink_row_marg_kernel(const float* __restrict__ K, const float* __restrict__ w,
                                     const float* __restrict__ u, float* __restrict__ arow, int ny) {
    int row = blockIdx.x * 8 + (threadIdx.x >> 5);
    int lane = threadIdx.x & 31;
    const float* Kr = K + (size_t)row * ny;
    float s = 0.f;
    for (int c = lane * 4; c < ny; c += 128) {
        float4 k = *(const float4*)&Kr[c];
        float4 ww = *(const float4*)&w[c];
        s += k.x * ww.x + k.y * ww.y + k.z * ww.z + k.w * ww.w;
    }
    s = warpSum(s);
    if (lane == 0) arow[row] = u[row] * s;
}

__global__ void sink_col_partial_kernel(const float* __restrict__ K, const float* __restrict__ u,
                                        float* __restrict__ ps, int nx, int ny, int chunk) {
    int col = blockIdx.x * blockDim.x + threadIdx.x;
    int r0 = blockIdx.y * chunk;
    int r1 = min(r0 + chunk, nx);
    float s = 0.f;
    for (int r = r0; r < r1; r += 4) {
        s += K[(size_t)r * ny + col] * __ldg(&u[r])
           + K[(size_t)(r + 1) * ny + col] * __ldg(&u[r + 1])
           + K[(size_t)(r + 2) * ny + col] * __ldg(&u[r + 2])
           + K[(size_t)(r + 3) * ny + col] * __ldg(&u[r + 3]);
    }
    ps[(size_t)blockIdx.y * ny + col] = s;
}

__global__ void sink_col_combine_kernel(const float* __restrict__ ps, float* __restrict__ w,
                                        int ny, int nch, float inv_n) {
    int col = blockIdx.x * blockDim.x + threadIdx.x;
    float s = 0.f;
    for (int c = 0; c < nch; c++) s += ps[(size_t)c * ny + col];
    w[col] = inv_n / s;
}

__global__ void logdiff_kernel(const float* __restrict__ a, const float* __restrict__ b,
                               float* __restrict__ out, int n) {
    int i = blockIdx.x * blockDim.x + threadIdx.x;
    if (i < n) out[i] = __logf(a[i]) - __logf(b[i]);
}

__global__ void marg_acc_kernel(const float* __restrict__ sums, int n, double* acc) {
    int i = blockIdx.x * blockDim.x + threadIdx.x;
    double t = 0.0;
    if (i < n) {
        float d = sums[i] - 1.f / (float)n;
        t = (double)d * (double)d;
    }
    t = blockSumD(t);
    if (threadIdx.x == 0) atomicAdd(&acc[S_MARG], t);
}

__global__ void sail_acc_kernel(const float* __restrict__ Mp, int n, int shift, double* acc) {
    size_t total4 = ((size_t)n * n) >> 2;
    double t = 0.0;
    for (size_t i4 = (size_t)blockIdx.x * blockDim.x + threadIdx.x; i4 < total4;
         i4 += (size_t)gridDim.x * blockDim.x) {
        size_t base = i4 * 4;
        int i = (int)(base >> shift);
        int j = (int)(base & (size_t)(n - 1));
        float4 m = *(const float4*)&Mp[base];
        float mv[4] = {m.x, m.y, m.z, m.w};
        float acc4 = 0.f;
        #pragma unroll
        for (int k = 0; k < 4; k++) {
            float z = mv[k] * 0.5f;
            if (j + k != i) z = -z;
            float a = -z;
            acc4 += fmaxf(a, 0.f) + log1pf(__expf(-fabsf(a)));
        }
        t += (double)acc4;
    }
    t = blockSumD(t);
    if (threadIdx.x == 0) atomicAdd(&acc[S_SAIL], t);
}

__global__ void diag_acc_kernel(const float* __restrict__ Mp, const float* __restrict__ u,
                                const float* __restrict__ v, int n, float logN, double* acc) {
    int i = blockIdx.x * blockDim.x + threadIdx.x;
    double ti = 0.0, te = 0.0;
    if (i < n) {
        float mii = Mp[(size_t)i * n + i];
        ti = (double)(mii - LSE_C + __logf(u[i]) + __logf(v[i]) + logN);
        te = (double)((1.f - mii * 0.05f) * 0.5f);
    }
    ti = blockSumD(ti);
    __shared__ double sh;
    if (threadIdx.x == 0) sh = ti;
    te = blockSumD(te);
    if (threadIdx.x == 0) {
        atomicAdd(&acc[S_IMP], sh);
        atomicAdd(&acc[S_EXP], te);
    }
}

__global__ void ot_acc_kernel(const float* __restrict__ Ka, const float* __restrict__ Ca,
                              const float* __restrict__ Mu,
                              const float* __restrict__ ua, const float* __restrict__ va,
                              const float* __restrict__ d, const float* __restrict__ e,
                              int n, int shift, double* acc) {
    size_t total4 = ((size_t)n * n) >> 2;
    double t = 0.0;
    for (size_t i4 = (size_t)blockIdx.x * blockDim.x + threadIdx.x; i4 < total4;
         i4 += (size_t)gridDim.x * blockDim.x) {
        size_t base = i4 * 4;
        int i = (int)(base >> shift);
        int j = (int)(base & (size_t)(n - 1));
        float4 k4 = *(const float4*)&Ka[base];
        float4 c4 = *(const float4*)&Ca[base];
        float4 m4 = *(const float4*)&Mu[base];
        float4 vj = *(const float4*)&va[j];
        float4 ej = *(const float4*)&e[j];
        float uai = __ldg(&ua[i]);
        float di = __ldg(&d[i]);
        float s = 0.f;
        s += k4.x * uai * vj.x * ((c4.x - m4.x) + di + ej.x);
        s += k4.y * uai * vj.y * ((c4.y - m4.y) + di + ej.y);
        s += k4.z * uai * vj.z * ((c4.z - m4.z) + di + ej.z);
        s += k4.w * uai * vj.w * ((c4.w - m4.w) + di + ej.w);
        t += (double)s;
    }
    t = blockSumD(t);
    if (threadIdx.x == 0) atomicAdd(&acc[S_OT], t);
}

__global__ void dot_acc_kernel(const float* __restrict__ A, const float* __restrict__ B,
                               int n, double* acc, int slot) {
    double t = 0.0;
    for (int i = blockIdx.x * blockDim.x + threadIdx.x; i < n; i += gridDim.x * blockDim.x)
        t += (double)A[i] * (double)B[i];
    t = blockSumD(t);
    if (threadIdx.x == 0) atomicAdd(&acc[slot], t);
}

__global__ void sumsq_acc_kernel(const float* __restrict__ A, int n, double* acc, int slot) {
    double t = 0.0;
    for (int i = blockIdx.x * blockDim.x + threadIdx.x; i < n; i += gridDim.x * blockDim.x)
        t += (double)A[i] * (double)A[i];
    t = blockSumD(t);
    if (threadIdx.x == 0) atomicAdd(&acc[slot], t);
}

__global__ void finalize_kernel(const double* __restrict__ acc, float* __restrict__ out) {
    double L = acc[S_MARG]
             + acc[S_SAIL] / ((double)NP * (double)NP)
             + acc[S_EXP] / (double)NP
             - acc[S_IMP] / (double)NP
             + acc[S_OT]
             + (acc[S_N1] + acc[S_N2] - 2.0 * acc[S_DT]) / ((double)NX * (double)NX)
             + (acc[S_SQA] + acc[S_SQB] - 2.0 * acc[S_SQG]);
    out[0] = (float)L;
}

// ---------------------------------------------------------------------------
// Host side
// ---------------------------------------------------------------------------
static float* g_partial = nullptr;   // set to g_Ca's address in kernel_launch

static inline void launch_gemm(int TA, int TB, const float* A, const float* B, float* C,
                               int M, int N, int K, int lda, int ldb, int ldc, float alpha,
                               float* Kout = nullptr, int S = 1) {
    dim3 block(256);
    if (S <= 1) {
        dim3 grid(N / 128, M / 128, 1);
        if (TA == 0 && TB == 0) gemm_mma_kernel<0, 0><<<grid, block>>>(A, B, C, Kout, K, lda, ldb, ldc, alpha, 0);
        else if (TA == 0 && TB == 1) gemm_mma_kernel<0, 1><<<grid, block>>>(A, B, C, Kout, K, lda, ldb, ldc, alpha, 0);
        else gemm_mma_kernel<1, 0><<<grid, block>>>(A, B, C, Kout, K, lda, ldb, ldc, alpha, 0);
    } else {
        int Kc = K / S;
        size_t mn = (size_t)M * N;
        dim3 grid(N / 128, M / 128, S);
        if (TA == 0 && TB == 0) gemm_mma_kernel<0, 0><<<grid, block>>>(A, B, g_partial, nullptr, Kc, lda, ldb, N, 1.f, mn);
        else if (TA == 0 && TB == 1) gemm_mma_kernel<0, 1><<<grid, block>>>(A, B, g_partial, nullptr, Kc, lda, ldb, N, 1.f, mn);
        else gemm_mma_kernel<1, 0><<<grid, block>>>(A, B, g_partial, nullptr, Kc, lda, ldb, N, 1.f, mn);
        splitk_reduce_kernel<<<((int)mn + 255) / 256, 256>>>(g_partial, C, (int)mn, S, alpha);
    }
}

static void run_sinkhorn_scaling(const float* K, float* u, float* w, int nx, int ny, float* ps) {
    float inv_a = 1.f / (float)nx, inv_b = 1.f / (float)ny;
    const int CH = 256;
    int nch = nx / CH;
    set_vec_kernel<<<(ny + 255) / 256, 256>>>(w, ny, 1.f);
    dim3 cgrid(ny / 256, nch);
    for (int it = 0; it < SINK_IT; it++) {
        sink_row_kernel<<<nx / 8, 256>>>(K, w, u, ny, inv_a);
        sink_col_partial_kernel<<<cgrid, 256>>>(K, u, ps, nx, ny, CH);
        sink_col_combine_kernel<<<ny / 256, 256>>>(ps, w, ny, nch, inv_b);
    }
}

#define GETSYM(ptr, sym) do { void* _t; cudaGetSymbolAddress(&_t, sym); ptr = (float*)_t; } while (0)

extern "C" void kernel_launch(void* const* d_in, const int* in_sizes, int n_in,
                              void* d_out, int out_size) {
    const float* fXp = (const float*)d_in[0];
    const float* fYp = (const float*)d_in[1];
    const float* X   = (const float*)d_in[2];
    const float* Y   = (const float*)d_in[3];
    const float* fX  = (const float*)d_in[4];
    const float* fY  = (const float*)d_in[5];
    const float* Xan = (const float*)d_in[6];
    const float* Yan = (const float*)d_in[7];
    float* out = (float*)d_out;

    float *Mp, *Kp, *Mu, *Ku, *Ca, *Ka, *Xa, *Ya, *Xu, *Yu, *Xn, *Yn, *fXn, *fYn, *fXpn, *fYpn;
    float *W, *T, *Sxx, *Syy, *Sxy, *Gxx, *Gyy, *Gfx, *Gfy, *Gxf, *Gfyy, *U1, *V1, *W1;
    float *Ag, *Bg, *Gg, *up, *wp, *uu, *wu, *ua, *wa, *arow, *bcol, *ap, *dv, *ev, *ps;
    double* acc;
    GETSYM(Mp, g_Mp); GETSYM(Kp, g_Kp); GETSYM(Mu, g_Mu); GETSYM(Ku, g_Ku);
    GETSYM(Ca, g_Ca); GETSYM(Ka, g_Ka);
    GETSYM(Xa, g_Xa); GETSYM(Ya, g_Ya); GETSYM(Xu, g_Xu); GETSYM(Yu, g_Yu);
    GETSYM(Xn, g_Xn); GETSYM(Yn, g_Yn); GETSYM(fXn, g_fXn); GETSYM(fYn, g_fYn);
    GETSYM(fXpn, g_fXpn); GETSYM(fYpn, g_fYpn);
    GETSYM(W, g_W); GETSYM(T, g_T);
    GETSYM(Sxx, g_Sxx); GETSYM(Syy, g_Syy); GETSYM(Sxy, g_Sxy);
    GETSYM(Gxx, g_Gxx); GETSYM(Gyy, g_Gyy); GETSYM(Gfx, g_Gfx); GETSYM(Gfy, g_Gfy);
    GETSYM(Gxf, g_Gxf); GETSYM(Gfyy, g_Gfyy); GETSYM(U1, g_U1); GETSYM(V1, g_V1); GETSYM(W1, g_W1);
    GETSYM(Ag, g_Ag); GETSYM(Bg, g_Bg); GETSYM(Gg, g_Gg);
    GETSYM(up, g_up); GETSYM(wp, g_wp); GETSYM(uu, g_uu); GETSYM(wu, g_wu);
    GETSYM(ua, g_ua); GETSYM(wa, g_wa);
    GETSYM(arow, g_arow); GETSYM(bcol, g_bcol); GETSYM(ap, g_ap);
    GETSYM(dv, g_dvec); GETSYM(ev, g_evec);
    GETSYM(ps, g_ps);
    { void* _t; cudaGetSymbolAddress(&_t, g_acc); acc = (double*)_t; }
    g_partial = Ca;   // g_Ca doubles as split-K partial scratch when free

    zero_acc_kernel<<<1, 32>>>(acc);                 // 1
    rownorm_kernel<<<NX / 8, 256>>>(fX, fXn, DF);    // 2
    rownorm_kernel<<<NX / 8, 256>>>(fY, fYn, DF);    // 3
    rownorm_kernel<<<NX / 8, 256>>>(Xan, Xa, DX);    // 4
    rownorm_kernel<<<NX / 8, 256>>>(Yan, Ya, DY);    // 5
    launch_gemm(0, 1, fXn, fYn, Mu, NX, NX, DF, DF, DF, NX, EPS_INV, Ku);  // 6 <- profiled

    rownorm_kernel<<<NP / 8, 256>>>(fXp, fXpn, DF);
    rownorm_kernel<<<NP / 8, 256>>>(fYp, fYpn, DF);
    rownorm_kernel<<<NX / 8, 256>>>(X, Xu, DX);
    rownorm_kernel<<<NX / 8, 256>>>(Y, Yu, DY);

    // --- anchor covariances (split-K; g_Ca free here) ---
    launch_gemm(1, 0, Xa, Xa, Sxx, DX, DX, NX, DX, DX, DX, 1.f / NX, nullptr, 16);
    launch_gemm(1, 0, Ya, Ya, Syy, DY, DY, NX, DY, DY, DY, 1.f / NX, nullptr, 16);
    launch_gemm(1, 0, Xa, Ya, Sxy, DX, DY, NX, DX, DY, DY, 1.f / NX, nullptr, 16);

    // --- pairs cosine matrix ---
    launch_gemm(0, 1, fXpn, fYpn, Mp, NP, NP, DF, DF, DF, NP, EPS_INV, Kp);

    // --- scaling-domain sinkhorns ---
    run_sinkhorn_scaling(Kp, up, wp, NP, NP, ps);
    run_sinkhorn_scaling(Ku, uu, wu, NX, NX, ps);

    // --- pairs plan stats (col marginal == 1/n exactly after final w update) ---
    sink_row_marg_kernel<<<NP / 8, 256>>>(Kp, wp, up, ap, NP);
    marg_acc_kernel<<<NP / 256, 256>>>(ap, NP, acc);
    sail_acc_kernel<<<1024, 256>>>(Mp, NP, 11, acc);
    diag_acc_kernel<<<NP / 256, 256>>>(Mp, up, wp, NP, logf((float)NP), acc);

    // --- latent plan marginals ---
    sink_row_marg_kernel<<<NX / 8, 256>>>(Ku, wu, uu, arow, NX);
    marg_acc_kernel<<<NX / 256, 256>>>(arow, NX, acc);
    set_vec_kernel<<<NX / 256, 256>>>(bcol, NX, 1.f / (float)NX);

    // --- anchor-space normalization + plan (g_Ca free until its GEMM) ---
    launch_gemm(0, 0, X, Sxx, W, NX, DX, DX, DX, DX, DX, 1.f);
    quadnorm_kernel<<<NX / 8, 256>>>(X, W, Xn, DX);
    launch_gemm(0, 0, Y, Syy, W, NX, DY, DY, DY, DY, DY, 1.f);
    quadnorm_kernel<<<NX / 8, 256>>>(Y, W, Yn, DY);
    launch_gemm(0, 0, Xn, Sxy, T, NX, DY, DX, DX, DY, DY, 1.f, nullptr, 2);
    launch_gemm(0, 1, T, Yn, Ca, NX, NX, DY, DY, DY, NX, EPS_INV, Ka);
    run_sinkhorn_scaling(Ka, ua, wa, NX, NX, ps);

    // --- L_ot ---
    logdiff_kernel<<<NX / 256, 256>>>(ua, uu, dv, NX);
    logdiff_kernel<<<NX / 256, 256>>>(wa, wu, ev, NX);
    ot_acc_kernel<<<2048, 256>>>(Ka, Ca, Mu, ua, wa, dv, ev, NX, 12, acc);

    // --- L_div (all split-K; g_Ca free after ot_acc) ---
    launch_gemm(1, 0, Xn, Xn, Gxx, DX, DX, NX, DX, DX, DX, 1.f, nullptr, 16);
    launch_gemm(1, 0, Yn, Yn, Gyy, DY, DY, NX, DY, DY, DY, 1.f, nullptr, 16);
    launch_gemm(1, 0, fXn, fXn, Gfx, DF, DF, NX, DF, DF, DF, 1.f, nullptr, 64);
    launch_gemm(1, 0, fYn, fYn, Gfy, DF, DF, NX, DF, DF, DF, 1.f, nullptr, 64);
    launch_gemm(1, 0, Xn, fXn, Gxf, DX, DF, NX, DX, DF, DF, 1.f, nullptr, 32);
    launch_gemm(1, 0, fYn, Yn, Gfyy, DF, DY, NX, DF, DY, DY, 1.f, nullptr, 32);
    launch_gemm(0, 0, Gxx, Sxy, U1, DX, DY, DX, DX, DY, DY, 1.f, nullptr, 12);
    launch_gemm(0, 0, U1, Gyy, V1, DX, DY, DY, DY, DY, DY, 1.f, nullptr, 8);
    launch_gemm(0, 0, Gxf, Gfyy, W1, DX, DY, DF, DF, DY, DY, 1.f, nullptr, 8);
    dot_acc_kernel<<<256, 256>>>(V1, Sxy, DX * DY, acc, S_N1);
    dot_acc_kernel<<<256, 256>>>(Gfx, Gfy, DF * DF, acc, S_N2);
    dot_acc_kernel<<<256, 256>>>(W1, Sxy, DX * DY, acc, S_DT);

    // --- L_gw ---
    scale_rows_sqrt_kernel<<<NX / 8, 256>>>(Xu, arow, W, DX);
    launch_gemm(1, 0, W, W, Ag, DX, DX, NX, DX, DX, DX, 1.f, nullptr, 16);
    sumsq_acc_kernel<<<256, 256>>>(Ag, DX * DX, acc, S_SQA);
    scale_rows_sqrt_kernel<<<NX / 8, 256>>>(Yu, bcol, W, DY);
    launch_gemm(1, 0, W, W, Bg, DY, DY, NX, DY, DY, DY, 1.f, nullptr, 16);
    sumsq_acc_kernel<<<256, 256>>>(Bg, DY * DY, acc, S_SQB);
    scale_rows_kernel<<<NX / 8, 256>>>(Yu, wu, W, DY);            // W = diag(w) Yu
    launch_gemm(0, 0, Ku, W, T, NX, DY, NX, NX, DY, DY, 1.f, nullptr, 4);  // T = Ku (w∘Yu)
    scale_rows_kernel<<<NX / 8, 256>>>(Xu, uu, Xa, DX);           // Xa = diag(u) Xu
    launch_gemm(1, 0, Xa, T, Gg, DX, DY, NX, DX, DY, DY, 1.f, nullptr, 16);
    sumsq_acc_kernel<<<256, 256>>>(Gg, DX * DY, acc, S_SQG);

    finalize_kernel<<<1, 1>>>(acc, out);
}

// round 12
// speedup vs baseline: 3.8471x; 1.0018x over previous
#include <cuda_runtime.h>
#include <cuda_bf16.h>
#include <math.h>
#include <stdint.h>

#define NP 2048
#define NX 4096
#define DX 768
#define DY 512
#define DF 256
#define EPS_INV 20.0f
#define SINK_IT 10
#define LSE_C 20.0f

#define S_MARG 0
#define S_SAIL 1
#define S_EXP  2
#define S_IMP  3
#define S_OT   4
#define S_N1   5
#define S_N2   6
#define S_DT   7
#define S_SQA  8
#define S_SQB  9
#define S_SQG  10

// ---------------------------------------------------------------------------
// Static device scratch
// ---------------------------------------------------------------------------
__device__ __align__(128) float g_Mp[(size_t)NP * NP];
__device__ __align__(128) float g_Kp[(size_t)NP * NP];
__device__ __align__(128) float g_Mu[(size_t)NX * NX];
__device__ __align__(128) float g_Ku[(size_t)NX * NX];
__device__ __align__(128) float g_Ca[(size_t)NX * NX];   // anchor log kernel + split-K partial scratch
__device__ __align__(128) float g_Ka[(size_t)NX * NX];
__device__ __align__(128) float g_Xa[NX * DX];
__device__ __align__(128) float g_Ya[NX * DY];
__device__ __align__(128) float g_Xu[NX * DX];
__device__ __align__(128) float g_Yu[NX * DY];
__device__ __align__(128) float g_Xn[NX * DX];
__device__ __align__(128) float g_Yn[NX * DY];
__device__ __align__(128) float g_fXn[NX * DF];
__device__ __align__(128) float g_fYn[NX * DF];
__device__ __align__(128) float g_fXpn[NP * DF];
__device__ __align__(128) float g_fYpn[NP * DF];
__device__ __align__(128) float g_W[NX * DX];
__device__ __align__(128) float g_T[NX * DY];
__device__ __align__(128) float g_Sxx[DX * DX];
__device__ __align__(128) float g_Syy[DY * DY];
__device__ __align__(128) float g_Sxy[DX * DY];
__device__ __align__(128) float g_Gxx[DX * DX];
__device__ __align__(128) float g_Gyy[DY * DY];
__device__ __align__(128) float g_Gfx[DF * DF];
__device__ __align__(128) float g_Gfy[DF * DF];
__device__ __align__(128) float g_Gxf[DX * DF];
__device__ __align__(128) float g_Gfyy[DF * DY];
__device__ __align__(128) float g_U1[DX * DY];
__device__ __align__(128) float g_V1[DX * DY];
__device__ __align__(128) float g_W1[DX * DY];
__device__ __align__(128) float g_Ag[DX * DX];
__device__ __align__(128) float g_Bg[DY * DY];
__device__ __align__(128) float g_Gg[DX * DY];
__device__ __align__(16) float g_up[NP], g_wp[NP];
__device__ __align__(16) float g_uu[NX], g_wu[NX];
__device__ __align__(16) float g_ua[NX], g_wa[NX];
__device__ __align__(16) float g_arow[NX], g_bcol[NX];
__device__ __align__(16) float g_ap[NP];
__device__ __align__(16) float g_dvec[NX], g_evec[NX];
__device__ __align__(128) float g_colacc[NX];
__device__ double g_acc[16];

// ---------------------------------------------------------------------------
// Reduction helpers
// ---------------------------------------------------------------------------
__device__ __forceinline__ float warpSum(float v) {
    #pragma unroll
    for (int o = 16; o; o >>= 1) v += __shfl_xor_sync(0xffffffffu, v, o);
    return v;
}
__device__ __forceinline__ double warpSumD(double v) {
    #pragma unroll
    for (int o = 16; o; o >>= 1) v += __shfl_xor_sync(0xffffffffu, v, o);
    return v;
}
__device__ double blockSumD(double v) {
    __shared__ double s[32];
    __syncthreads();
    int lane = threadIdx.x & 31, wid = threadIdx.x >> 5;
    v = warpSumD(v);
    if (lane == 0) s[wid] = v;
    __syncthreads();
    if (wid == 0) {
        int nw = blockDim.x >> 5;
        v = (lane < nw) ? s[lane] : 0.0;
        v = warpSumD(v);
    }
    return v;
}

// ---------------------------------------------------------------------------
// Tensor-core GEMM, split-bf16 (bf16x3), double-buffered smem, split-K.
// ---------------------------------------------------------------------------
#define ASTRIDE 24

__device__ __forceinline__ void bsplit(float x, __nv_bfloat16& h, __nv_bfloat16& l) {
    h = __float2bfloat16(x);
    l = __float2bfloat16(x - __bfloat162float(h));
}
__device__ __forceinline__ uint32_t bpack(__nv_bfloat16 a, __nv_bfloat16 b) {
    __nv_bfloat162 t; t.x = a; t.y = b;
    return *reinterpret_cast<uint32_t*>(&t);
}
__device__ __forceinline__ void mma16816(float* c, const uint32_t* a, const uint32_t* b) {
    asm volatile(
        "mma.sync.aligned.m16n8k16.row.col.f32.bf16.bf16.f32 "
        "{%0,%1,%2,%3}, {%4,%5,%6,%7}, {%8,%9}, {%0,%1,%2,%3};\n"
        : "+f"(c[0]), "+f"(c[1]), "+f"(c[2]), "+f"(c[3])
        : "r"(a[0]), "r"(a[1]), "r"(a[2]), "r"(a[3]), "r"(b[0]), "r"(b[1]));
}

template <int TA, int TB>
__global__ __launch_bounds__(256, 2)
void gemm_mma_kernel(const float* __restrict__ A, const float* __restrict__ B,
                     float* __restrict__ C, float* __restrict__ Kout,
                     int Kc, int lda, int ldb, int ldc, float alpha, size_t mnsize) {
    __shared__ __align__(16) __nv_bfloat16 Ash[2][128][ASTRIDE];
    __shared__ __align__(16) __nv_bfloat16 Asl[2][128][ASTRIDE];
    __shared__ __align__(16) __nv_bfloat16 Bsh[2][128][ASTRIDE];
    __shared__ __align__(16) __nv_bfloat16 Bsl[2][128][ASTRIDE];

    const int tid = threadIdx.x;
    const int warp = tid >> 5, lane = tid & 31;
    const int bm = blockIdx.y * 128, bn = blockIdx.x * 128;
    const int wm = (warp >> 2) * 64;
    const int wn = (warp & 3) * 32;
    const int kbeg = blockIdx.z * Kc;
    const int kend = kbeg + Kc;
    C += (size_t)blockIdx.z * mnsize;

    float acc[4][4][4];
    #pragma unroll
    for (int mi = 0; mi < 4; mi++)
        #pragma unroll
        for (int ni = 0; ni < 4; ni++)
            #pragma unroll
            for (int e = 0; e < 4; e++) acc[mi][ni][e] = 0.f;

    float4 va[2], vb[2];

    auto load_tiles = [&](int k0) {
        #pragma unroll
        for (int i = 0; i < 2; i++) {
            int f = tid * 2 + i;
            if (TA == 0) {
                int row = f >> 2, c4 = (f & 3) * 4;
                va[i] = *(const float4*)&A[(size_t)(bm + row) * lda + k0 + c4];
            } else {
                int kr = f >> 5, m0 = (f & 31) * 4;
                va[i] = *(const float4*)&A[(size_t)(k0 + kr) * lda + bm + m0];
            }
            if (TB == 1) {
                int row = f >> 2, c4 = (f & 3) * 4;
                vb[i] = *(const float4*)&B[(size_t)(bn + row) * ldb + k0 + c4];
            } else {
                int kr = f >> 5, n0 = (f & 31) * 4;
                vb[i] = *(const float4*)&B[(size_t)(k0 + kr) * ldb + bn + n0];
            }
        }
    };
    auto stage_tiles = [&](int p) {
        #pragma unroll
        for (int i = 0; i < 2; i++) {
            int f = tid * 2 + i;
            float4 v = va[i];
            if (TA == 0) {
                int row = f >> 2, c4 = (f & 3) * 4;
                __nv_bfloat16 h0, h1, h2, h3, l0, l1, l2, l3;
                bsplit(v.x, h0, l0); bsplit(v.y, h1, l1);
                bsplit(v.z, h2, l2); bsplit(v.w, h3, l3);
                *(uint2*)&Ash[p][row][c4] = make_uint2(bpack(h0, h1), bpack(h2, h3));
                *(uint2*)&Asl[p][row][c4] = make_uint2(bpack(l0, l1), bpack(l2, l3));
            } else {
                int kr = f >> 5, m0 = (f & 31) * 4;
                __nv_bfloat16 h, l;
                bsplit(v.x, h, l); Ash[p][m0 + 0][kr] = h; Asl[p][m0 + 0][kr] = l;
                bsplit(v.y, h, l); Ash[p][m0 + 1][kr] = h; Asl[p][m0 + 1][kr] = l;
                bsplit(v.z, h, l); Ash[p][m0 + 2][kr] = h; Asl[p][m0 + 2][kr] = l;
                bsplit(v.w, h, l); Ash[p][m0 + 3][kr] = h; Asl[p][m0 + 3][kr] = l;
            }
            v = vb[i];
            if (TB == 1) {
                int row = f >> 2, c4 = (f & 3) * 4;
                __nv_bfloat16 h0, h1, h2, h3, l0, l1, l2, l3;
                bsplit(v.x, h0, l0); bsplit(v.y, h1, l1);
                bsplit(v.z, h2, l2); bsplit(v.w, h3, l3);
                *(uint2*)&Bsh[p][row][c4] = make_uint2(bpack(h0, h1), bpack(h2, h3));
                *(uint2*)&Bsl[p][row][c4] = make_uint2(bpack(l0, l1), bpack(l2, l3));
            } else {
                int kr = f >> 5, n0 = (f & 31) * 4;
                __nv_bfloat16 h, l;
                bsplit(v.x, h, l); Bsh[p][n0 + 0][kr] = h; Bsl[p][n0 + 0][kr] = l;
                bsplit(v.y, h, l); Bsh[p][n0 + 1][kr] = h; Bsl[p][n0 + 1][kr] = l;
                bsplit(v.z, h, l); Bsh[p][n0 + 2][kr] = h; Bsl[p][n0 + 2][kr] = l;
                bsplit(v.w, h, l); Bsh[p][n0 + 3][kr] = h; Bsl[p][n0 + 3][kr] = l;
            }
        }
    };
    auto compute = [&](int p) {
        const int fr = lane >> 2;
        const int fc = (lane & 3) * 2;
        uint32_t bh[4][2], bl[4][2];
        #pragma unroll
        for (int ni = 0; ni < 4; ni++) {
            int nr = wn + ni * 8 + fr;
            bh[ni][0] = *(const uint32_t*)&Bsh[p][nr][fc];
            bh[ni][1] = *(const uint32_t*)&Bsh[p][nr][fc + 8];
            bl[ni][0] = *(const uint32_t*)&Bsl[p][nr][fc];
            bl[ni][1] = *(const uint32_t*)&Bsl[p][nr][fc + 8];
        }
        #pragma unroll
        for (int mi = 0; mi < 4; mi++) {
            int r0 = wm + mi * 16 + fr;
            uint32_t ah[4], al[4];
            ah[0] = *(const uint32_t*)&Ash[p][r0][fc];
            ah[1] = *(const uint32_t*)&Ash[p][r0 + 8][fc];
            ah[2] = *(const uint32_t*)&Ash[p][r0][fc + 8];
            ah[3] = *(const uint32_t*)&Ash[p][r0 + 8][fc + 8];
            al[0] = *(const uint32_t*)&Asl[p][r0][fc];
            al[1] = *(const uint32_t*)&Asl[p][r0 + 8][fc];
            al[2] = *(const uint32_t*)&Asl[p][r0][fc + 8];
            al[3] = *(const uint32_t*)&Asl[p][r0 + 8][fc + 8];
            #pragma unroll
            for (int ni = 0; ni < 4; ni++) {
                mma16816(acc[mi][ni], ah, bh[ni]);
                mma16816(acc[mi][ni], ah, bl[ni]);
                mma16816(acc[mi][ni], al, bh[ni]);
            }
        }
    };

    load_tiles(kbeg);
    stage_tiles(0);
    __syncthreads();
    int p = 0;
    for (int k0 = kbeg; k0 < kend; k0 += 16) {
        bool has_next = (k0 + 16 < kend);
        if (has_next) load_tiles(k0 + 16);
        compute(p);
        if (has_next) {
            stage_tiles(p ^ 1);
            __syncthreads();
            p ^= 1;
        }
    }

    const int fr = lane >> 2;
    const int fc = (lane & 3) * 2;
    #pragma unroll
    for (int mi = 0; mi < 4; mi++) {
        int r = bm + wm + mi * 16 + fr;
        #pragma unroll
        for (int ni = 0; ni < 4; ni++) {
            int c = bn + wn + ni * 8 + fc;
            float v0 = alpha * acc[mi][ni][0];
            float v1 = alpha * acc[mi][ni][1];
            float v2 = alpha * acc[mi][ni][2];
            float v3 = alpha * acc[mi][ni][3];
            *(float2*)&C[(size_t)r * ldc + c] = make_float2(v0, v1);
            *(float2*)&C[(size_t)(r + 8) * ldc + c] = make_float2(v2, v3);
            if (Kout) {
                *(float2*)&Kout[(size_t)r * ldc + c] =
                    make_float2(__expf(v0 - LSE_C), __expf(v1 - LSE_C));
                *(float2*)&Kout[(size_t)(r + 8) * ldc + c] =
                    make_float2(__expf(v2 - LSE_C), __expf(v3 - LSE_C));
            }
        }
    }
}

__global__ void splitk_reduce_kernel(const float* __restrict__ p, float* __restrict__ C,
                                     int mn, int S, float alpha) {
    int i = blockIdx.x * blockDim.x + threadIdx.x;
    if (i < mn) {
        float s = 0.f;
        for (int z = 0; z < S; z++) s += p[(size_t)z * mn + i];
        C[i] = alpha * s;
    }
}

// ---------------------------------------------------------------------------
// Elementwise / reduction kernels
// ---------------------------------------------------------------------------
__global__ void zero_acc_kernel(double* a) { if (threadIdx.x < 16) a[threadIdx.x] = 0.0; }
__global__ void set_vec_kernel(float* p, int n, float val) {
    int i = blockIdx.x * blockDim.x + threadIdx.x;
    if (i < n) p[i] = val;
}

__global__ void rownorm_kernel(const float* __restrict__ in, float* __restrict__ out, int D) {
    int row = blockIdx.x * 8 + (threadIdx.x >> 5);
    int lane = threadIdx.x & 31;
    const float* r = in + (size_t)row * D;
    float ss = 0.f;
    for (int i = lane * 4; i < D; i += 128) {
        float4 v = *(const float4*)&r[i];
        ss += v.x * v.x + v.y * v.y + v.z * v.z + v.w * v.w;
    }
    ss = warpSum(ss);
    float inv = 1.f / fmaxf(sqrtf(ss), 1e-8f);
    for (int i = lane * 4; i < D; i += 128) {
        float4 v = *(const float4*)&r[i];
        v.x *= inv; v.y *= inv; v.z *= inv; v.w *= inv;
        *(float4*)&out[(size_t)row * D + i] = v;
    }
}

__global__ void quadnorm_kernel(const float* __restrict__ X, const float* __restrict__ W,
                                float* __restrict__ out, int D) {
    int row = blockIdx.x * 8 + (threadIdx.x >> 5);
    int lane = threadIdx.x & 31;
    const float* xr = X + (size_t)row * D;
    const float* wr = W + (size_t)row * D;
    float ss = 0.f;
    for (int i = lane * 4; i < D; i += 128) {
        float4 a = *(const float4*)&xr[i];
        float4 b = *(const float4*)&wr[i];
        ss += a.x * b.x + a.y * b.y + a.z * b.z + a.w * b.w;
    }
    ss = warpSum(ss);
    float inv = 1.f / fmaxf(sqrtf(ss), 1e-8f);
    for (int i = lane * 4; i < D; i += 128) {
        float4 v = *(const float4*)&xr[i];
        v.x *= inv; v.y *= inv; v.z *= inv; v.w *= inv;
        *(float4*)&out[(size_t)row * D + i] = v;
    }
}

__global__ void scale_rows_sqrt_kernel(const float* __restrict__ X, const float* __restrict__ a,
                                       float* __restrict__ out, int D) {
    int row = blockIdx.x * 8 + (threadIdx.x >> 5);
    int lane = threadIdx.x & 31;
    float sc = sqrtf(fmaxf(a[row], 0.f));
    for (int i = lane * 4; i < D; i += 128) {
        float4 v = *(const float4*)&X[(size_t)row * D + i];
        v.x *= sc; v.y *= sc; v.z *= sc; v.w *= sc;
        *(float4*)&out[(size_t)row * D + i] = v;
    }
}

__global__ void scale_rows_kernel(const float* __restrict__ X, const float* __restrict__ a,
                                  float* __restrict__ out, int D) {
    int row = blockIdx.x * 8 + (threadIdx.x >> 5);
    int lane = threadIdx.x & 31;
    float sc = a[row];
    for (int i = lane * 4; i < D; i += 128) {
        float4 v = *(const float4*)&X[(size_t)row * D + i];
        v.x *= sc; v.y *= sc; v.z *= sc; v.w *= sc;
        *(float4*)&out[(size_t)row * D + i] = v;
    }
}

// ---- fused scaling-domain Sinkhorn iteration ----
// Block handles NROWS rows: row phase computes u = inv_a/(K w) (warp per row),
// col phase accumulates partial K^T u into colacc via atomics.
template <int NROWS>
__global__ void sink_iter_kernel(const float* __restrict__ K, const float* __restrict__ w,
                                 float* __restrict__ u, float* __restrict__ colacc,
                                 int ny, float inv_a) {
    __shared__ float su[NROWS];
    int warp = threadIdx.x >> 5, lane = threadIdx.x & 31;
    int rbase = blockIdx.x * NROWS;
    #pragma unroll
    for (int rr = warp; rr < NROWS; rr += 8) {
        int row = rbase + rr;
        const float* Kr = K + (size_t)row * ny;
        float s = 0.f;
        for (int c = lane * 4; c < ny; c += 128) {
            float4 k = *(const float4*)&Kr[c];
            float4 ww = *(const float4*)&w[c];
            s += k.x * ww.x + k.y * ww.y + k.z * ww.z + k.w * ww.w;
        }
        s = warpSum(s);
        if (lane == 0) { float uv = inv_a / s; u[row] = uv; su[rr] = uv; }
    }
    __syncthreads();
    for (int col = threadIdx.x; col < ny; col += 256) {
        float s = 0.f;
        #pragma unroll 8
        for (int rr = 0; rr < NROWS; rr++)
            s += K[(size_t)(rbase + rr) * ny + col] * su[rr];
        atomicAdd(&colacc[col], s);
    }
}

// w = inv_b / colacc ; colacc = 0
__global__ void sink_norm_kernel(float* __restrict__ colacc, float* __restrict__ w,
                                 int ny, float inv_b) {
    int i = blockIdx.x * blockDim.x + threadIdx.x;
    if (i < ny) {
        w[i] = inv_b / colacc[i];
        colacc[i] = 0.f;
    }
}

// arow[i] = u[i] * sum_j K[i,j]*w[j]
__global__ void sink_row_marg_kernel(const float* __restrict__ K, const float* __restrict__ w,
                                     const float* __restrict__ u, float* __restrict__ arow, int ny) {
    int row = blockIdx.x * 8 + (threadIdx.x >> 5);
    int lane = threadIdx.x & 31;
    const float* Kr = K + (size_t)row * ny;
    float s = 0.f;
    for (int c = lane * 4; c < ny; c += 128) {
        float4 k = *(const float4*)&Kr[c];
        float4 ww = *(const float4*)&w[c];
        s += k.x * ww.x + k.y * ww.y + k.z * ww.z + k.w * ww.w;
    }
    s = warpSum(s);
    if (lane == 0) arow[row] = u[row] * s;
}

__global__ void logdiff_kernel(const float* __restrict__ a, const float* __restrict__ b,
                               float* __restrict__ out, int n) {
    int i = blockIdx.x * blockDim.x + threadIdx.x;
    if (i < n) out[i] = __logf(a[i]) - __logf(b[i]);
}

__global__ void marg_acc_kernel(const float* __restrict__ sums, int n, double* acc) {
    int i = blockIdx.x * blockDim.x + threadIdx.x;
    double t = 0.0;
    if (i < n) {
        float d = sums[i] - 1.f / (float)n;
        t = (double)d * (double)d;
    }
    t = blockSumD(t);
    if (threadIdx.x == 0) atomicAdd(&acc[S_MARG], t);
}

__global__ void sail_acc_kernel(const float* __restrict__ Mp, int n, int shift, double* acc) {
    size_t total4 = ((size_t)n * n) >> 2;
    double t = 0.0;
    for (size_t i4 = (size_t)blockIdx.x * blockDim.x + threadIdx.x; i4 < total4;
         i4 += (size_t)gridDim.x * blockDim.x) {
        size_t base = i4 * 4;
        int i = (int)(base >> shift);
        int j = (int)(base & (size_t)(n - 1));
        float4 m = *(const float4*)&Mp[base];
        float mv[4] = {m.x, m.y, m.z, m.w};
        float acc4 = 0.f;
        #pragma unroll
        for (int k = 0; k < 4; k++) {
            float z = mv[k] * 0.5f;
            if (j + k != i) z = -z;
            float a = -z;
            acc4 += fmaxf(a, 0.f) + log1pf(__expf(-fabsf(a)));
        }
        t += (double)acc4;
    }
    t = blockSumD(t);
    if (threadIdx.x == 0) atomicAdd(&acc[S_SAIL], t);
}

__global__ void diag_acc_kernel(const float* __restrict__ Mp, const float* __restrict__ u,
                                const float* __restrict__ v, int n, float logN, double* acc) {
    int i = blockIdx.x * blockDim.x + threadIdx.x;
    double ti = 0.0, te = 0.0;
    if (i < n) {
        float mii = Mp[(size_t)i * n + i];
        ti = (double)(mii - LSE_C + __logf(u[i]) + __logf(v[i]) + logN);
        te = (double)((1.f - mii * 0.05f) * 0.5f);
    }
    ti = blockSumD(ti);
    __shared__ double sh;
    if (threadIdx.x == 0) sh = ti;
    te = blockSumD(te);
    if (threadIdx.x == 0) {
        atomicAdd(&acc[S_IMP], sh);
        atomicAdd(&acc[S_EXP], te);
    }
}

__global__ void ot_acc_kernel(const float* __restrict__ Ka, const float* __restrict__ Ca,
                              const float* __restrict__ Mu,
                              const float* __restrict__ ua, const float* __restrict__ va,
                              const float* __restrict__ d, const float* __restrict__ e,
                              int n, int shift, double* acc) {
    size_t total4 = ((size_t)n * n) >> 2;
    double t = 0.0;
    for (size_t i4 = (size_t)blockIdx.x * blockDim.x + threadIdx.x; i4 < total4;
         i4 += (size_t)gridDim.x * blockDim.x) {
        size_t base = i4 * 4;
        int i = (int)(base >> shift);
        int j = (int)(base & (size_t)(n - 1));
        float4 k4 = *(const float4*)&Ka[base];
        float4 c4 = *(const float4*)&Ca[base];
        float4 m4 = *(const float4*)&Mu[base];
        float4 vj = *(const float4*)&va[j];
        float4 ej = *(const float4*)&e[j];
        float uai = __ldg(&ua[i]);
        float di = __ldg(&d[i]);
        float s = 0.f;
        s += k4.x * uai * vj.x * ((c4.x - m4.x) + di + ej.x);
        s += k4.y * uai * vj.y * ((c4.y - m4.y) + di + ej.y);
        s += k4.z * uai * vj.z * ((c4.z - m4.z) + di + ej.z);
        s += k4.w * uai * vj.w * ((c4.w - m4.w) + di + ej.w);
        t += (double)s;
    }
    t = blockSumD(t);
    if (threadIdx.x == 0) atomicAdd(&acc[S_OT], t);
}

__global__ void dot_acc_kernel(const float* __restrict__ A, const float* __restrict__ B,
                               int n, double* acc, int slot) {
    double t = 0.0;
    for (int i = blockIdx.x * blockDim.x + threadIdx.x; i < n; i += gridDim.x * blockDim.x)
        t += (double)A[i] * (double)B[i];
    t = blockSumD(t);
    if (threadIdx.x == 0) atomicAdd(&acc[slot], t);
}

__global__ void sumsq_acc_kernel(const float* __restrict__ A, int n, double* acc, int slot) {
    double t = 0.0;
    for (int i = blockIdx.x * blockDim.x + threadIdx.x; i < n; i += gridDim.x * blockDim.x)
        t += (double)A[i] * (double)A[i];
    t = blockSumD(t);
    if (threadIdx.x == 0) atomicAdd(&acc[slot], t);
}

__global__ void finalize_kernel(const double* __restrict__ acc, float* __restrict__ out) {
    double L = acc[S_MARG]
             + acc[S_SAIL] / ((double)NP * (double)NP)
             + acc[S_EXP] / (double)NP
             - acc[S_IMP] / (double)NP
             + acc[S_OT]
             + (acc[S_N1] + acc[S_N2] - 2.0 * acc[S_DT]) / ((double)NX * (double)NX)
             + (acc[S_SQA] + acc[S_SQB] - 2.0 * acc[S_SQG]);
    out[0] = (float)L;
}

// ---------------------------------------------------------------------------
// Host side
// ---------------------------------------------------------------------------
static float* g_partial = nullptr;

static inline void launch_gemm(int TA, int TB, const float* A, const float* B, float* C,
                               int M, int N, int K, int lda, int ldb, int ldc, float alpha,
                               float* Kout = nullptr, int S = 1) {
    dim3 block(256);
    if (S <= 1) {
        dim3 grid(N / 128, M / 128, 1);
        if (TA == 0 && TB == 0) gemm_mma_kernel<0, 0><<<grid, block>>>(A, B, C, Kout, K, lda, ldb, ldc, alpha, 0);
        else if (TA == 0 && TB == 1) gemm_mma_kernel<0, 1><<<grid, block>>>(A, B, C, Kout, K, lda, ldb, ldc, alpha, 0);
        else gemm_mma_kernel<1, 0><<<grid, block>>>(A, B, C, Kout, K, lda, ldb, ldc, alpha, 0);
    } else {
        int Kc = K / S;
        size_t mn = (size_t)M * N;
        dim3 grid(N / 128, M / 128, S);
        if (TA == 0 && TB == 0) gemm_mma_kernel<0, 0><<<grid, block>>>(A, B, g_partial, nullptr, Kc, lda, ldb, N, 1.f, mn);
        else if (TA == 0 && TB == 1) gemm_mma_kernel<0, 1><<<grid, block>>>(A, B, g_partial, nullptr, Kc, lda, ldb, N, 1.f, mn);
        else gemm_mma_kernel<1, 0><<<grid, block>>>(A, B, g_partial, nullptr, Kc, lda, ldb, N, 1.f, mn);
        splitk_reduce_kernel<<<((int)mn + 255) / 256, 256>>>(g_partial, C, (int)mn, S, alpha);
    }
}

static void run_sinkhorn_scaling(const float* K, float* u, float* w, float* colacc,
                                 int nx, int ny) {
    float inv_a = 1.f / (float)nx, inv_b = 1.f / (float)ny;
    set_vec_kernel<<<(ny + 255) / 256, 256>>>(w, ny, 1.f);
    set_vec_kernel<<<(ny + 255) / 256, 256>>>(colacc, ny, 0.f);
    for (int it = 0; it < SINK_IT; it++) {
        if (nx >= 4096)
            sink_iter_kernel<32><<<nx / 32, 256>>>(K, w, u, colacc, ny, inv_a);
        else
            sink_iter_kernel<8><<<nx / 8, 256>>>(K, w, u, colacc, ny, inv_a);
        sink_norm_kernel<<<(ny + 255) / 256, 256>>>(colacc, w, ny, inv_b);
    }
}

#define GETSYM(ptr, sym) do { void* _t; cudaGetSymbolAddress(&_t, sym); ptr = (float*)_t; } while (0)

extern "C" void kernel_launch(void* const* d_in, const int* in_sizes, int n_in,
                              void* d_out, int out_size) {
    const float* fXp = (const float*)d_in[0];
    const float* fYp = (const float*)d_in[1];
    const float* X   = (const float*)d_in[2];
    const float* Y   = (const float*)d_in[3];
    const float* fX  = (const float*)d_in[4];
    const float* fY  = (const float*)d_in[5];
    const float* Xan = (const float*)d_in[6];
    const float* Yan = (const float*)d_in[7];
    float* out = (float*)d_out;

    float *Mp, *Kp, *Mu, *Ku, *Ca, *Ka, *Xa, *Ya, *Xu, *Yu, *Xn, *Yn, *fXn, *fYn, *fXpn, *fYpn;
    float *W, *T, *Sxx, *Syy, *Sxy, *Gxx, *Gyy, *Gfx, *Gfy, *Gxf, *Gfyy, *U1, *V1, *W1;
    float *Ag, *Bg, *Gg, *up, *wp, *uu, *wu, *ua, *wa, *arow, *bcol, *ap, *dv, *ev, *colacc;
    double* acc;
    GETSYM(Mp, g_Mp); GETSYM(Kp, g_Kp); GETSYM(Mu, g_Mu); GETSYM(Ku, g_Ku);
    GETSYM(Ca, g_Ca); GETSYM(Ka, g_Ka);
    GETSYM(Xa, g_Xa); GETSYM(Ya, g_Ya); GETSYM(Xu, g_Xu); GETSYM(Yu, g_Yu);
    GETSYM(Xn, g_Xn); GETSYM(Yn, g_Yn); GETSYM(fXn, g_fXn); GETSYM(fYn, g_fYn);
    GETSYM(fXpn, g_fXpn); GETSYM(fYpn, g_fYpn);
    GETSYM(W, g_W); GETSYM(T, g_T);
    GETSYM(Sxx, g_Sxx); GETSYM(Syy, g_Syy); GETSYM(Sxy, g_Sxy);
    GETSYM(Gxx, g_Gxx); GETSYM(Gyy, g_Gyy); GETSYM(Gfx, g_Gfx); GETSYM(Gfy, g_Gfy);
    GETSYM(Gxf, g_Gxf); GETSYM(Gfyy, g_Gfyy); GETSYM(U1, g_U1); GETSYM(V1, g_V1); GETSYM(W1, g_W1);
    GETSYM(Ag, g_Ag); GETSYM(Bg, g_Bg); GETSYM(Gg, g_Gg);
    GETSYM(up, g_up); GETSYM(wp, g_wp); GETSYM(uu, g_uu); GETSYM(wu, g_wu);
    GETSYM(ua, g_ua); GETSYM(wa, g_wa);
    GETSYM(arow, g_arow); GETSYM(bcol, g_bcol); GETSYM(ap, g_ap);
    GETSYM(dv, g_dvec); GETSYM(ev, g_evec);
    GETSYM(colacc, g_colacc);
    { void* _t; cudaGetSymbolAddress(&_t, g_acc); acc = (double*)_t; }
    g_partial = Ca;

    zero_acc_kernel<<<1, 32>>>(acc);                 // 1
    rownorm_kernel<<<NX / 8, 256>>>(fX, fXn, DF);    // 2
    rownorm_kernel<<<NX / 8, 256>>>(fY, fYn, DF);    // 3
    rownorm_kernel<<<NX / 8, 256>>>(Xan, Xa, DX);    // 4
    launch_gemm(0, 1, fXn, fYn, Mu, NX, NX, DF, DF, DF, NX, EPS_INV, Ku);  // 5 <- profile target
    rownorm_kernel<<<NX / 8, 256>>>(Yan, Ya, DY);    // 6

    rownorm_kernel<<<NP / 8, 256>>>(fXp, fXpn, DF);
    rownorm_kernel<<<NP / 8, 256>>>(fYp, fYpn, DF);
    rownorm_kernel<<<NX / 8, 256>>>(X, Xu, DX);
    rownorm_kernel<<<NX / 8, 256>>>(Y, Yu, DY);

    // --- anchor covariances (split-K; g_Ca free here) ---
    launch_gemm(1, 0, Xa, Xa, Sxx, DX, DX, NX, DX, DX, DX, 1.f / NX, nullptr, 16);
    launch_gemm(1, 0, Ya, Ya, Syy, DY, DY, NX, DY, DY, DY, 1.f / NX, nullptr, 16);
    launch_gemm(1, 0, Xa, Ya, Sxy, DX, DY, NX, DX, DY, DY, 1.f / NX, nullptr, 16);

    // --- pairs cosine matrix ---
    launch_gemm(0, 1, fXpn, fYpn, Mp, NP, NP, DF, DF, DF, NP, EPS_INV, Kp);

    // --- scaling-domain sinkhorns (fused iterations) ---
    run_sinkhorn_scaling(Kp, up, wp, colacc, NP, NP);
    run_sinkhorn_scaling(Ku, uu, wu, colacc, NX, NX);

    // --- pairs plan stats (col marginal == 1/n exactly after final w update) ---
    sink_row_marg_kernel<<<NP / 8, 256>>>(Kp, wp, up, ap, NP);
    marg_acc_kernel<<<NP / 256, 256>>>(ap, NP, acc);
    sail_acc_kernel<<<1024, 256>>>(Mp, NP, 11, acc);
    diag_acc_kernel<<<NP / 256, 256>>>(Mp, up, wp, NP, logf((float)NP), acc);

    // --- latent plan marginals ---
    sink_row_marg_kernel<<<NX / 8, 256>>>(Ku, wu, uu, arow, NX);
    marg_acc_kernel<<<NX / 256, 256>>>(arow, NX, acc);
    set_vec_kernel<<<NX / 256, 256>>>(bcol, NX, 1.f / (float)NX);

    // --- anchor-space normalization + plan ---
    launch_gemm(0, 0, X, Sxx, W, NX, DX, DX, DX, DX, DX, 1.f);
    quadnorm_kernel<<<NX / 8, 256>>>(X, W, Xn, DX);
    launch_gemm(0, 0, Y, Syy, W, NX, DY, DY, DY, DY, DY, 1.f);
    quadnorm_kernel<<<NX / 8, 256>>>(Y, W, Yn, DY);
    launch_gemm(0, 0, Xn, Sxy, T, NX, DY, DX, DX, DY, DY, 1.f, nullptr, 2);
    launch_gemm(0, 1, T, Yn, Ca, NX, NX, DY, DY, DY, NX, EPS_INV, Ka);
    run_sinkhorn_scaling(Ka, ua, wa, colacc, NX, NX);

    // --- L_ot ---
    logdiff_kernel<<<NX / 256, 256>>>(ua, uu, dv, NX);
    logdiff_kernel<<<NX / 256, 256>>>(wa, wu, ev, NX);
    ot_acc_kernel<<<2048, 256>>>(Ka, Ca, Mu, ua, wa, dv, ev, NX, 12, acc);

    // --- L_div (split-K; g_Ca free after ot_acc) ---
    launch_gemm(1, 0, Xn, Xn, Gxx, DX, DX, NX, DX, DX, DX, 1.f, nullptr, 16);
    launch_gemm(1, 0, Yn, Yn, Gyy, DY, DY, NX, DY, DY, DY, 1.f, nullptr, 16);
    launch_gemm(1, 0, fXn, fXn, Gfx, DF, DF, NX, DF, DF, DF, 1.f, nullptr, 64);
    launch_gemm(1, 0, fYn, fYn, Gfy, DF, DF, NX, DF, DF, DF, 1.f, nullptr, 64);
    launch_gemm(1, 0, Xn, fXn, Gxf, DX, DF, NX, DX, DF, DF, 1.f, nullptr, 32);
    launch_gemm(1, 0, fYn, Yn, Gfyy, DF, DY, NX, DF, DY, DY, 1.f, nullptr, 32);
    launch_gemm(0, 0, Gxx, Sxy, U1, DX, DY, DX, DX, DY, DY, 1.f, nullptr, 12);
    launch_gemm(0, 0, U1, Gyy, V1, DX, DY, DY, DY, DY, DY, 1.f, nullptr, 8);
    launch_gemm(0, 0, Gxf, Gfyy, W1, DX, DY, DF, DF, DY, DY, 1.f, nullptr, 8);
    dot_acc_kernel<<<256, 256>>>(V1, Sxy, DX * DY, acc, S_N1);
    dot_acc_kernel<<<256, 256>>>(Gfx, Gfy, DF * DF, acc, S_N2);
    dot_acc_kernel<<<256, 256>>>(W1, Sxy, DX * DY, acc, S_DT);

    // --- L_gw ---
    scale_rows_sqrt_kernel<<<NX / 8, 256>>>(Xu, arow, W, DX);
    launch_gemm(1, 0, W, W, Ag, DX, DX, NX, DX, DX, DX, 1.f, nullptr, 16);
    sumsq_acc_kernel<<<256, 256>>>(Ag, DX * DX, acc, S_SQA);
    scale_rows_sqrt_kernel<<<NX / 8, 256>>>(Yu, bcol, W, DY);
    launch_gemm(1, 0, W, W, Bg, DY, DY, NX, DY, DY, DY, 1.f, nullptr, 16);
    sumsq_acc_kernel<<<256, 256>>>(Bg, DY * DY, acc, S_SQB);
    scale_rows_kernel<<<NX / 8, 256>>>(Yu, wu, W, DY);
    launch_gemm(0, 0, Ku, W, T, NX, DY, NX, NX, DY, DY, 1.f, nullptr, 4);
    scale_rows_kernel<<<NX / 8, 256>>>(Xu, uu, Xa, DX);
    launch_gemm(1, 0, Xa, T, Gg, DX, DY, NX, DX, DY, DY, 1.f, nullptr, 16);
    sumsq_acc_kernel<<<256, 256>>>(Gg, DX * DY, acc, S_SQG);

    finalize_kernel<<<1, 1>>>(acc, out);
}